// round 5
// baseline (speedup 1.0000x reference)
#include <cuda_runtime.h>
#include <cuda_bf16.h>
#include <cstdint>

// Problem constants
#define N_APP  100000
#define N_ATTR 50000
#define D      128

// ---------------- device scratch (no allocation allowed) ----------------
__device__ float g_n0[(size_t)N_ATTR * D];
__device__ float g_n1[(size_t)N_APP * D];
__device__ float g_n2[(size_t)N_APP * D];
__device__ float g_hattr[(size_t)N_ATTR * D];
__device__ float g_happ[(size_t)N_APP * D];
__device__ float g_deg0[N_ATTR];
__device__ float g_deg1[N_APP];
__device__ float g_deg2[N_APP];
__device__ float g_pattr[(size_t)N_ATTR * 2];
__device__ float g_papp[(size_t)N_APP * 4];
__device__ float g_q1[(size_t)N_APP * 2];
__device__ float g_q2[(size_t)N_APP * 2];
__device__ float g_bsum1[D];       // b1[1]+b1[2]
__device__ float g_Wn1c[D * 2];    // Wneigh2[1] @ Wc
__device__ float g_Wapp4[D * 4];   // cols 0..1: (Wself2[1]+Wself2[2])@Wc ; cols 2..3: Wneigh2[2]@Wc
__device__ float g_bce[2];         // (b2[1]+b2[2])@Wc + bc
// pre-swizzled bf16 weight tiles: B stored [n=128][k=128] row-major (256B rows),
// 16B-chunk XOR swizzle (chunk ^= row&7). tiles: 0=Wself1[0], 1=Wneigh1[0],
// 2=Wself1[1]+Wself1[2], 3=Wneigh1[1], 4=Wneigh1[2]
__device__ uint2 g_Bhi[5 * 4096];
__device__ uint2 g_Blo[5 * 4096];

// ---------------- PTX helpers ----------------
__device__ __forceinline__ uint32_t smem_u32(const void* p) {
    uint32_t a;
    asm("{ .reg .u64 t; cvta.to.shared.u64 t, %1; cvt.u32.u64 %0, t; }" : "=r"(a) : "l"(p));
    return a;
}
__device__ __forceinline__ void ldsm_x4(uint32_t* r, uint32_t addr) {
    asm volatile("ldmatrix.sync.aligned.m8n8.x4.shared.b16 {%0,%1,%2,%3}, [%4];"
                 : "=r"(r[0]), "=r"(r[1]), "=r"(r[2]), "=r"(r[3]) : "r"(addr));
}
__device__ __forceinline__ void mma_bf16(float* c, const uint32_t* a, uint32_t b0, uint32_t b1) {
    asm volatile("mma.sync.aligned.m16n8k16.row.col.f32.bf16.bf16.f32 "
                 "{%0,%1,%2,%3}, {%4,%5,%6,%7}, {%8,%9}, {%0,%1,%2,%3};"
                 : "+f"(c[0]), "+f"(c[1]), "+f"(c[2]), "+f"(c[3])
                 : "r"(a[0]), "r"(a[1]), "r"(a[2]), "r"(a[3]), "r"(b0), "r"(b1));
}
__device__ __forceinline__ uint32_t bf2u(__nv_bfloat162 v) {
    return *reinterpret_cast<uint32_t*>(&v);
}
// swizzled byte offset for row-major [128][128] bf16 tile (256B rows, 16B chunks)
__device__ __forceinline__ uint32_t swz_off(int row, int chunk16, int byte_in) {
    return (uint32_t)row * 256u + (uint32_t)((chunk16 ^ (row & 7)) << 4) + (uint32_t)byte_in;
}

// ---------------- red helpers ----------------
__device__ __forceinline__ void red_add_v4(float* addr, float4 v) {
    asm volatile("red.global.add.v4.f32 [%0], {%1,%2,%3,%4};"
                 :: "l"(addr), "f"(v.x), "f"(v.y), "f"(v.z), "f"(v.w) : "memory");
}
__device__ __forceinline__ void red_add_v2(float* addr, float a, float b) {
    asm volatile("red.global.add.v2.f32 [%0], {%1,%2};"
                 :: "l"(addr), "f"(a), "f"(b) : "memory");
}

// ---------------- small-weight prep ----------------
__global__ void prep_kernel(const float* __restrict__ b1,
                            const float* __restrict__ Wself2, const float* __restrict__ Wneigh2,
                            const float* __restrict__ b2,
                            const float* __restrict__ Wc, const float* __restrict__ bc)
{
    int tid = threadIdx.x;
    if (tid < D) g_bsum1[tid] = b1[128 + tid] + b1[256 + tid];
    {
        int i = tid >> 1, j = tid & 1;
        float s_sc = 0.f, s_n2 = 0.f, s_n1 = 0.f;
        #pragma unroll 4
        for (int l = 0; l < D; l++) {
            float wc = Wc[l * 2 + j];
            s_sc += (Wself2[16384 + i * D + l] + Wself2[32768 + i * D + l]) * wc;
            s_n2 += Wneigh2[32768 + i * D + l] * wc;
            s_n1 += Wneigh2[16384 + i * D + l] * wc;
        }
        g_Wapp4[i * 4 + j]     = s_sc;
        g_Wapp4[i * 4 + 2 + j] = s_n2;
        g_Wn1c[i * 2 + j]      = s_n1;
    }
    if (tid < 2) {
        float s = bc[tid];
        for (int l = 0; l < D; l++) s += (b2[128 + l] + b2[256 + l]) * Wc[l * 2 + tid];
        g_bce[tid] = s;
    }
}

// ---------------- weight tiles: transpose + hi/lo bf16 split + pre-swizzle ----------------
__global__ void prep_weights(const float* __restrict__ Wself1, const float* __restrict__ Wneigh1)
{
    int m = blockIdx.x;              // tile id 0..4
    int tid = threadIdx.x;
    for (int idx = tid; idx < 4096; idx += 256) {
        int n = idx >> 5;            // output-channel row 0..127
        int cg = idx & 31;           // uint2 (4 bf16) group along k
        int k0 = cg * 4;
        float w[4];
        #pragma unroll
        for (int i = 0; i < 4; i++) {
            int k = k0 + i;
            float v;
            if      (m == 0) v = Wself1[k * D + n];
            else if (m == 1) v = Wneigh1[k * D + n];
            else if (m == 2) v = Wself1[16384 + k * D + n] + Wself1[32768 + k * D + n];
            else if (m == 3) v = Wneigh1[16384 + k * D + n];
            else             v = Wneigh1[32768 + k * D + n];
            w[i] = v;
        }
        __nv_bfloat162 h01 = __floats2bfloat162_rn(w[0], w[1]);
        __nv_bfloat162 h23 = __floats2bfloat162_rn(w[2], w[3]);
        float2 f01 = __bfloat1622float2(h01), f23 = __bfloat1622float2(h23);
        __nv_bfloat162 l01 = __floats2bfloat162_rn(w[0] - f01.x, w[1] - f01.y);
        __nv_bfloat162 l23 = __floats2bfloat162_rn(w[2] - f23.x, w[3] - f23.y);
        uint32_t off = swz_off(n, cg >> 1, (cg & 1) << 3);
        g_Bhi[m * 4096 + (off >> 3)] = make_uint2(bf2u(h01), bf2u(h23));
        g_Blo[m * 4096 + (off >> 3)] = make_uint2(bf2u(l01), bf2u(l23));
    }
}

// ---------------- fused edge scatter: all 3 relations in one launch ----------------
__global__ void __launch_bounds__(256) scatter_all(
    const float4* __restrict__ f0, const int* __restrict__ s0, const int* __restrict__ d0,
    const float* __restrict__ w0, float4* __restrict__ a0, float* __restrict__ dg0,
    const float4* __restrict__ f1, const int* __restrict__ s1, const int* __restrict__ d1,
    const float* __restrict__ w1, float4* __restrict__ a1, float* __restrict__ dg1,
    const float4* __restrict__ f2, const int* __restrict__ s2, const int* __restrict__ d2,
    const float* __restrict__ w2, float4* __restrict__ a2, float* __restrict__ dg2,
    int E, int wpr)
{
    int gw = (blockIdx.x * 256 + threadIdx.x) >> 5;
    int lane = threadIdx.x & 31;
    int rel = gw / wpr;
    if (rel >= 3) return;
    int e0 = (gw - rel * wpr) * 8;
    if (e0 >= E) return;
    int n = E - e0; if (n > 8) n = 8;

    const float4* feat; const int* src; const int* dst; const float* ew; float4* acc; float* deg;
    if (rel == 0)      { feat = f0; src = s0; dst = d0; ew = w0; acc = a0; deg = dg0; }
    else if (rel == 1) { feat = f1; src = s1; dst = d1; ew = w1; acc = a1; deg = dg1; }
    else               { feat = f2; src = s2; dst = d2; ew = w2; acc = a2; deg = dg2; }

    int s_ = 0, d_ = 0; float w_ = 0.f;
    if (lane < n) {
        s_ = __ldg(&src[e0 + lane]);
        d_ = __ldg(&dst[e0 + lane]);
        w_ = __ldg(&ew[e0 + lane]);
    }
    float4 v[8];
    #pragma unroll
    for (int i = 0; i < 8; i++) {
        int s = __shfl_sync(0xffffffffu, s_, i);
        if (i < n) v[i] = feat[(size_t)s * 32 + lane];
    }
    #pragma unroll
    for (int i = 0; i < 8; i++) {
        int d   = __shfl_sync(0xffffffffu, d_, i);
        float w = __shfl_sync(0xffffffffu, w_, i);
        if (i < n) {
            float4 t = v[i];
            t.x *= w; t.y *= w; t.z *= w; t.w *= w;
            red_add_v4((float*)(acc + (size_t)d * 32 + lane), t);
        }
    }
    if (lane < n) atomicAdd(deg + d_, 1.0f);
}

// ---------------- tensor-core GEMM via mma.sync (HMMA bf16, hi/lo split) ----------------
// C[M,128] = relu(sum_b scale_b(A_b) @ W_b + bias). 128x128 CTA tile, 8 warps (4x2),
// per warp 32x64, K=128 per input block staged in smem, 3 mma terms (hh, hl, lh).
#define OFF_AHI   0
#define OFF_ALO   32768
#define OFF_BHI   65536
#define OFF_BLO   98304
#define OFF_BIAS  131072
#define GEMM_SMEM 131584

__global__ void __launch_bounds__(256) gemm_tc(
    const float* __restrict__ A0, const float* __restrict__ dg0, const uint4* __restrict__ B0h, const uint4* __restrict__ B0l,
    const float* __restrict__ A1, const float* __restrict__ dg1, const uint4* __restrict__ B1h, const uint4* __restrict__ B1l,
    const float* __restrict__ A2, const float* __restrict__ dg2, const uint4* __restrict__ B2h, const uint4* __restrict__ B2l,
    const float* __restrict__ bias, float* __restrict__ C, int M, int nblk)
{
    extern __shared__ __align__(1024) char smem[];
    const uint32_t sb = smem_u32(smem);
    const int tid = threadIdx.x;
    const int wid = tid >> 5, lane = tid & 31;
    const int m0 = blockIdx.x * 128;
    const int mw = wid >> 1;     // 0..3 (M warp row)
    const int nw = wid & 1;      // 0..1 (N warp col)

    if (tid < 128) ((float*)(smem + OFF_BIAS))[tid] = bias[tid];

    float acc[2][8][4];
    #pragma unroll
    for (int i = 0; i < 2; i++)
        #pragma unroll
        for (int j = 0; j < 8; j++)
            #pragma unroll
            for (int q = 0; q < 4; q++) acc[i][j][q] = 0.f;

    const float* Ap[3] = {A0, A1, A2};
    const float* Dp[3] = {dg0, dg1, dg2};
    const uint4* Bh[3] = {B0h, B1h, B2h};
    const uint4* Bl[3] = {B0l, B1l, B2l};

    // per-lane fragment addressing constants
    const int a_rowl = lane & 15;         // row within m16 tile
    const int a_half = lane >> 4;         // k chunk half
    const int b_rowl = (lane & 7) + ((lane >> 4) << 3);  // row within n16 tile
    const int b_half = (lane >> 3) & 1;   // k chunk half

    for (int blk = 0; blk < nblk; blk++) {
        __syncthreads();
        // ---- stage B (pre-swizzled, straight copy) ----
        {
            const uint4* bh = Bh[blk];
            const uint4* bl = Bl[blk];
            uint4* dsth = (uint4*)(smem + OFF_BHI);
            uint4* dstl = (uint4*)(smem + OFF_BLO);
            #pragma unroll
            for (int i = 0; i < 8; i++) {
                int t = tid + i * 256;
                dsth[t] = __ldg(&bh[t]);
                dstl[t] = __ldg(&bl[t]);
            }
        }
        // ---- stage A: fp32 -> bf16 hi/lo, swizzled ----
        {
            const float* A = Ap[blk];
            const float* dgp = Dp[blk];
            #pragma unroll
            for (int j = 0; j < 16; j++) {
                int f = tid + j * 256;
                int row = f >> 5, cg = f & 31;
                int grow = m0 + row;
                float4 a = make_float4(0.f, 0.f, 0.f, 0.f);
                float sc = 1.f;
                if (grow < M) {
                    a = *(const float4*)(A + (size_t)grow * 128 + cg * 4);
                    if (dgp) sc = 1.f / fmaxf(__ldg(&dgp[grow]), 1.f);
                }
                float x0 = a.x * sc, x1 = a.y * sc, x2 = a.z * sc, x3 = a.w * sc;
                __nv_bfloat162 h01 = __floats2bfloat162_rn(x0, x1);
                __nv_bfloat162 h23 = __floats2bfloat162_rn(x2, x3);
                float2 f01 = __bfloat1622float2(h01), f23 = __bfloat1622float2(h23);
                __nv_bfloat162 l01 = __floats2bfloat162_rn(x0 - f01.x, x1 - f01.y);
                __nv_bfloat162 l23 = __floats2bfloat162_rn(x2 - f23.x, x3 - f23.y);
                uint32_t off = swz_off(row, cg >> 1, (cg & 1) << 3);
                *(uint2*)(smem + OFF_AHI + off) = make_uint2(bf2u(h01), bf2u(h23));
                *(uint2*)(smem + OFF_ALO + off) = make_uint2(bf2u(l01), bf2u(l23));
            }
        }
        __syncthreads();

        // ---- compute: 8 k-steps of k16 ----
        #pragma unroll
        for (int ks = 0; ks < 8; ks++) {
            uint32_t ah[2][4], al[2][4];
            #pragma unroll
            for (int mt = 0; mt < 2; mt++) {
                int r = mw * 32 + mt * 16 + a_rowl;
                uint32_t off = swz_off(r, 2 * ks + a_half, 0);
                ldsm_x4(ah[mt], sb + OFF_AHI + off);
                ldsm_x4(al[mt], sb + OFF_ALO + off);
            }
            #pragma unroll
            for (int nb = 0; nb < 4; nb++) {
                int r = nw * 64 + nb * 16 + b_rowl;
                uint32_t off = swz_off(r, 2 * ks + b_half, 0);
                uint32_t bh[4], bl[4];
                ldsm_x4(bh, sb + OFF_BHI + off);
                ldsm_x4(bl, sb + OFF_BLO + off);
                #pragma unroll
                for (int mt = 0; mt < 2; mt++) {
                    mma_bf16(acc[mt][nb * 2 + 0], ah[mt], bh[0], bh[1]);
                    mma_bf16(acc[mt][nb * 2 + 1], ah[mt], bh[2], bh[3]);
                    mma_bf16(acc[mt][nb * 2 + 0], ah[mt], bl[0], bl[1]);
                    mma_bf16(acc[mt][nb * 2 + 1], ah[mt], bl[2], bl[3]);
                    mma_bf16(acc[mt][nb * 2 + 0], al[mt], bh[0], bh[1]);
                    mma_bf16(acc[mt][nb * 2 + 1], al[mt], bh[2], bh[3]);
                }
            }
        }
    }

    // ---- epilogue: bias + relu + store ----
    const float* bias_s = (const float*)(smem + OFF_BIAS);
    #pragma unroll
    for (int mt = 0; mt < 2; mt++) {
        int r0 = m0 + mw * 32 + mt * 16 + (lane >> 2);
        #pragma unroll
        for (int nt = 0; nt < 8; nt++) {
            int col = nw * 64 + nt * 8 + (lane & 3) * 2;
            float b0 = bias_s[col], b1 = bias_s[col + 1];
            if (r0 < M) {
                float2 v;
                v.x = fmaxf(acc[mt][nt][0] + b0, 0.f);
                v.y = fmaxf(acc[mt][nt][1] + b1, 0.f);
                *(float2*)(C + (size_t)r0 * 128 + col) = v;
            }
            if (r0 + 8 < M) {
                float2 v;
                v.x = fmaxf(acc[mt][nt][2] + b0, 0.f);
                v.y = fmaxf(acc[mt][nt][3] + b1, 0.f);
                *(float2*)(C + (size_t)(r0 + 8) * 128 + col) = v;
            }
        }
    }
}

// ---------------- projection: P[M,NC] = H[M,128] @ W[128,NC]  (warp per row) ----------------
template <int NC>
__global__ void __launch_bounds__(256) proj_kernel(const float4* __restrict__ H,
                                                   const float* __restrict__ W,
                                                   float* __restrict__ P, int M)
{
    __shared__ float Ws[128 * NC];
    for (int i = threadIdx.x; i < 128 * NC; i += 256) Ws[i] = W[i];
    __syncthreads();
    int warp = (blockIdx.x * 256 + threadIdx.x) >> 5;
    int lane = threadIdx.x & 31;
    if (warp >= M) return;
    float4 h = H[(size_t)warp * 32 + lane];
    int k = lane * 4;
    float acc[NC];
    #pragma unroll
    for (int c = 0; c < NC; c++)
        acc[c] = h.x * Ws[(k + 0) * NC + c] + h.y * Ws[(k + 1) * NC + c]
               + h.z * Ws[(k + 2) * NC + c] + h.w * Ws[(k + 3) * NC + c];
    #pragma unroll
    for (int c = 0; c < NC; c++)
        #pragma unroll
        for (int o = 16; o > 0; o >>= 1) acc[c] += __shfl_xor_sync(0xffffffffu, acc[c], o);
    if (lane == 0) {
        #pragma unroll
        for (int c = 0; c < NC; c++) P[(size_t)warp * NC + c] = acc[c];
    }
}

// ---------------- 2-wide edge scatter on projected features ----------------
__global__ void __launch_bounds__(256) scatter_proj(
    const float* __restrict__ P, int stride, int off,
    const int* __restrict__ src, const int* __restrict__ dst, const float* __restrict__ ew,
    float* __restrict__ Q, int E)
{
    int e = blockIdx.x * 256 + threadIdx.x;
    if (e >= E) return;
    int s = src[e], d = dst[e];
    float w = ew[e];
    float a = P[(size_t)s * stride + off]     * w;
    float b = P[(size_t)s * stride + off + 1] * w;
    red_add_v2(Q + (size_t)d * 2, a, b);
}

// ---------------- finalize ----------------
__global__ void __launch_bounds__(256) finalize_kernel(float* __restrict__ out)
{
    int v = blockIdx.x * 256 + threadIdx.x;
    if (v >= N_APP) return;
    float i1 = 1.0f / fmaxf(g_deg1[v], 1.0f);
    float i2 = 1.0f / fmaxf(g_deg2[v], 1.0f);
    out[v * 2 + 0] = g_papp[v * 4 + 0] + g_q1[v * 2 + 0] * i1 + g_q2[v * 2 + 0] * i2 + g_bce[0];
    out[v * 2 + 1] = g_papp[v * 4 + 1] + g_q1[v * 2 + 1] * i1 + g_q2[v * 2 + 1] * i2 + g_bce[1];
}

// ---------------- launch ----------------
extern "C" void kernel_launch(void* const* d_in, const int* in_sizes, int n_in,
                              void* d_out, int out_size)
{
    const float* x_app   = (const float*)d_in[0];
    const float* x_attr  = (const float*)d_in[1];
    const float* ew0     = (const float*)d_in[2];
    const float* ew1     = (const float*)d_in[3];
    const float* ew2     = (const float*)d_in[4];
    const float* Wself1  = (const float*)d_in[5];
    const float* Wneigh1 = (const float*)d_in[6];
    const float* b1      = (const float*)d_in[7];
    const float* Wself2  = (const float*)d_in[8];
    const float* Wneigh2 = (const float*)d_in[9];
    const float* b2      = (const float*)d_in[10];
    const float* Wc      = (const float*)d_in[11];
    const float* bc      = (const float*)d_in[12];
    const int* src0 = (const int*)d_in[13];
    const int* dst0 = (const int*)d_in[14];
    const int* src1 = (const int*)d_in[15];
    const int* dst1 = (const int*)d_in[16];
    const int* src2 = (const int*)d_in[17];
    const int* dst2 = (const int*)d_in[18];
    float* out = (float*)d_out;
    const int E = in_sizes[2];

    float *n0, *n1, *n2, *hattr, *happ, *deg0, *deg1, *deg2, *pattr, *papp, *q1, *q2;
    float *bsum1, *Wn1c, *Wapp4;
    uint2 *Bhi, *Blo;
    cudaGetSymbolAddress((void**)&n0, g_n0);
    cudaGetSymbolAddress((void**)&n1, g_n1);
    cudaGetSymbolAddress((void**)&n2, g_n2);
    cudaGetSymbolAddress((void**)&hattr, g_hattr);
    cudaGetSymbolAddress((void**)&happ, g_happ);
    cudaGetSymbolAddress((void**)&deg0, g_deg0);
    cudaGetSymbolAddress((void**)&deg1, g_deg1);
    cudaGetSymbolAddress((void**)&deg2, g_deg2);
    cudaGetSymbolAddress((void**)&pattr, g_pattr);
    cudaGetSymbolAddress((void**)&papp, g_papp);
    cudaGetSymbolAddress((void**)&q1, g_q1);
    cudaGetSymbolAddress((void**)&q2, g_q2);
    cudaGetSymbolAddress((void**)&bsum1, g_bsum1);
    cudaGetSymbolAddress((void**)&Wn1c, g_Wn1c);
    cudaGetSymbolAddress((void**)&Wapp4, g_Wapp4);
    cudaGetSymbolAddress((void**)&Bhi, g_Bhi);
    cudaGetSymbolAddress((void**)&Blo, g_Blo);

    cudaFuncSetAttribute(gemm_tc, cudaFuncAttributeMaxDynamicSharedMemorySize, GEMM_SMEM);

    cudaMemsetAsync(n0, 0, sizeof(g_n0), 0);
    cudaMemsetAsync(n1, 0, sizeof(g_n1), 0);
    cudaMemsetAsync(n2, 0, sizeof(g_n2), 0);
    cudaMemsetAsync(deg0, 0, sizeof(g_deg0), 0);
    cudaMemsetAsync(deg1, 0, sizeof(g_deg1), 0);
    cudaMemsetAsync(deg2, 0, sizeof(g_deg2), 0);
    cudaMemsetAsync(q1, 0, sizeof(g_q1), 0);
    cudaMemsetAsync(q2, 0, sizeof(g_q2), 0);

    prep_kernel<<<1, 256>>>(b1, Wself2, Wneigh2, b2, Wc, bc);
    prep_weights<<<5, 256>>>(Wself1, Wneigh1);

    // fused layer-1 aggregation (3 relations, warp per 8 edges)
    int wpr = (E + 7) / 8;
    int sblocks = (3 * wpr * 32 + 255) / 256;
    scatter_all<<<sblocks, 256>>>(
        (const float4*)x_app,  src0, dst0, ew0, (float4*)n0, deg0,
        (const float4*)x_attr, src1, dst1, ew1, (float4*)n1, deg1,
        (const float4*)x_app,  src2, dst2, ew2, (float4*)n2, deg2,
        E, wpr);

    // layer-1 GEMMs on tensor cores (mma.sync bf16 hi/lo split)
    gemm_tc<<<(N_ATTR + 127) / 128, 256, GEMM_SMEM>>>(
        x_attr, nullptr, (const uint4*)(Bhi + 0 * 4096), (const uint4*)(Blo + 0 * 4096),
        n0, deg0,        (const uint4*)(Bhi + 1 * 4096), (const uint4*)(Blo + 1 * 4096),
        nullptr, nullptr, nullptr, nullptr,
        b1, hattr, N_ATTR, 2);
    gemm_tc<<<(N_APP + 127) / 128, 256, GEMM_SMEM>>>(
        x_app, nullptr, (const uint4*)(Bhi + 2 * 4096), (const uint4*)(Blo + 2 * 4096),
        n1, deg1,       (const uint4*)(Bhi + 3 * 4096), (const uint4*)(Blo + 3 * 4096),
        n2, deg2,       (const uint4*)(Bhi + 4 * 4096), (const uint4*)(Blo + 4 * 4096),
        bsum1, happ, N_APP, 3);

    // layer 2 folded to low-dim projections
    proj_kernel<2><<<(N_ATTR * 32 + 255) / 256, 256>>>((const float4*)hattr, Wn1c, pattr, N_ATTR);
    proj_kernel<4><<<(N_APP * 32 + 255) / 256, 256>>>((const float4*)happ, Wapp4, papp, N_APP);

    int eblocks = (E + 255) / 256;
    scatter_proj<<<eblocks, 256>>>(pattr, 2, 0, src1, dst1, ew1, q1, E);
    scatter_proj<<<eblocks, 256>>>(papp,  4, 2, src2, dst2, ew2, q2, E);

    finalize_kernel<<<(N_APP + 255) / 256, 256>>>(out);
}

// round 6
// speedup vs baseline: 1.2546x; 1.2546x over previous
#include <cuda_runtime.h>
#include <cuda_bf16.h>
#include <cstdint>

// Problem constants
#define N_APP  100000
#define N_ATTR 50000
#define D      128

// ---------------- device scratch (no allocation allowed) ----------------
__device__ float g_n0[(size_t)N_ATTR * D];
__device__ float g_n1[(size_t)N_APP * D];
__device__ float g_n2[(size_t)N_APP * D];
__device__ float g_hattr[(size_t)N_ATTR * D];
__device__ float g_happ[(size_t)N_APP * D];
__device__ float g_deg0[N_ATTR];
__device__ float g_deg1[N_APP];
__device__ float g_deg2[N_APP];
__device__ float g_pattr[(size_t)N_ATTR * 2];
__device__ float g_papp[(size_t)N_APP * 4];
__device__ float g_q1[(size_t)N_APP * 2];
__device__ float g_q2[(size_t)N_APP * 2];
__device__ float g_bsum1[D];       // b1[1]+b1[2]
__device__ float g_Wn1c[D * 2];    // Wneigh2[1] @ Wc
__device__ float g_Wapp4[D * 4];   // cols 0..1: (Wself2[1]+Wself2[2])@Wc ; cols 2..3: Wneigh2[2]@Wc
__device__ float g_bce[2];         // (b2[1]+b2[2])@Wc + bc
// pre-swizzled bf16 weight tiles, stored per K-half:
// tile = [half(2)][n=128][k-half=64] bf16; within a half rows are 128B, 8x16B chunks,
// chunk ^= n&7 swizzle. tiles: 0=Wself1[0], 1=Wneigh1[0], 2=Wself1[1]+Wself1[2],
// 3=Wneigh1[1], 4=Wneigh1[2]
__device__ uint2 g_Bhi[5 * 4096];
__device__ uint2 g_Blo[5 * 4096];

// ---------------- PTX helpers ----------------
__device__ __forceinline__ uint32_t smem_u32(const void* p) {
    uint32_t a;
    asm("{ .reg .u64 t; cvta.to.shared.u64 t, %1; cvt.u32.u64 %0, t; }" : "=r"(a) : "l"(p));
    return a;
}
__device__ __forceinline__ void ldsm_x4(uint32_t* r, uint32_t addr) {
    asm volatile("ldmatrix.sync.aligned.m8n8.x4.shared.b16 {%0,%1,%2,%3}, [%4];"
                 : "=r"(r[0]), "=r"(r[1]), "=r"(r[2]), "=r"(r[3]) : "r"(addr));
}
__device__ __forceinline__ void mma_bf16(float* c, const uint32_t* a, uint32_t b0, uint32_t b1) {
    asm volatile("mma.sync.aligned.m16n8k16.row.col.f32.bf16.bf16.f32 "
                 "{%0,%1,%2,%3}, {%4,%5,%6,%7}, {%8,%9}, {%0,%1,%2,%3};"
                 : "+f"(c[0]), "+f"(c[1]), "+f"(c[2]), "+f"(c[3])
                 : "r"(a[0]), "r"(a[1]), "r"(a[2]), "r"(a[3]), "r"(b0), "r"(b1));
}
__device__ __forceinline__ void cp_async16(uint32_t dst, const void* src) {
    asm volatile("cp.async.cg.shared.global [%0], [%1], 16;" :: "r"(dst), "l"(src) : "memory");
}
__device__ __forceinline__ void cp_async_commit_wait() {
    asm volatile("cp.async.commit_group;" ::: "memory");
    asm volatile("cp.async.wait_group 0;" ::: "memory");
}
__device__ __forceinline__ uint32_t bf2u(__nv_bfloat162 v) {
    return *reinterpret_cast<uint32_t*>(&v);
}
// swizzled byte offset within one K-half tile: [128 rows][64 bf16] = 128B rows, 8 chunks
__device__ __forceinline__ uint32_t swz_off(int row, int chunk16, int byte_in) {
    return (uint32_t)row * 128u + (uint32_t)((chunk16 ^ (row & 7)) << 4) + (uint32_t)byte_in;
}

// ---------------- red helpers ----------------
__device__ __forceinline__ void red_add_v4(float* addr, float4 v) {
    asm volatile("red.global.add.v4.f32 [%0], {%1,%2,%3,%4};"
                 :: "l"(addr), "f"(v.x), "f"(v.y), "f"(v.z), "f"(v.w) : "memory");
}
__device__ __forceinline__ void red_add_v2(float* addr, float a, float b) {
    asm volatile("red.global.add.v2.f32 [%0], {%1,%2};"
                 :: "l"(addr), "f"(a), "f"(b) : "memory");
}

// ---------------- small-weight prep ----------------
__global__ void prep_kernel(const float* __restrict__ b1,
                            const float* __restrict__ Wself2, const float* __restrict__ Wneigh2,
                            const float* __restrict__ b2,
                            const float* __restrict__ Wc, const float* __restrict__ bc)
{
    int tid = threadIdx.x;
    if (tid < D) g_bsum1[tid] = b1[128 + tid] + b1[256 + tid];
    {
        int i = tid >> 1, j = tid & 1;
        float s_sc = 0.f, s_n2 = 0.f, s_n1 = 0.f;
        #pragma unroll 4
        for (int l = 0; l < D; l++) {
            float wc = Wc[l * 2 + j];
            s_sc += (Wself2[16384 + i * D + l] + Wself2[32768 + i * D + l]) * wc;
            s_n2 += Wneigh2[32768 + i * D + l] * wc;
            s_n1 += Wneigh2[16384 + i * D + l] * wc;
        }
        g_Wapp4[i * 4 + j]     = s_sc;
        g_Wapp4[i * 4 + 2 + j] = s_n2;
        g_Wn1c[i * 2 + j]      = s_n1;
    }
    if (tid < 2) {
        float s = bc[tid];
        for (int l = 0; l < D; l++) s += (b2[128 + l] + b2[256 + l]) * Wc[l * 2 + tid];
        g_bce[tid] = s;
    }
}

// ---------------- weight tiles: transpose + hi/lo bf16 split + per-half pre-swizzle ----------------
__global__ void prep_weights(const float* __restrict__ Wself1, const float* __restrict__ Wneigh1)
{
    int m = blockIdx.x;              // tile id 0..4
    int tid = threadIdx.x;
    for (int idx = tid; idx < 4096; idx += 256) {
        int n = idx >> 5;            // output-channel row 0..127
        int cg = idx & 31;           // uint2 (4 bf16) group along k
        int k0 = cg * 4;
        float w[4];
        #pragma unroll
        for (int i = 0; i < 4; i++) {
            int k = k0 + i;
            float v;
            if      (m == 0) v = Wself1[k * D + n];
            else if (m == 1) v = Wneigh1[k * D + n];
            else if (m == 2) v = Wself1[16384 + k * D + n] + Wself1[32768 + k * D + n];
            else if (m == 3) v = Wneigh1[16384 + k * D + n];
            else             v = Wneigh1[32768 + k * D + n];
            w[i] = v;
        }
        __nv_bfloat162 h01 = __floats2bfloat162_rn(w[0], w[1]);
        __nv_bfloat162 h23 = __floats2bfloat162_rn(w[2], w[3]);
        float2 f01 = __bfloat1622float2(h01), f23 = __bfloat1622float2(h23);
        __nv_bfloat162 l01 = __floats2bfloat162_rn(w[0] - f01.x, w[1] - f01.y);
        __nv_bfloat162 l23 = __floats2bfloat162_rn(w[2] - f23.x, w[3] - f23.y);
        int half = cg >> 4;                    // k0 >= 64 ?
        int cgi  = cg & 15;                    // uint2 group within half
        uint32_t off = (uint32_t)half * 16384u + swz_off(n, cgi >> 1, (cgi & 1) << 3);
        g_Bhi[m * 4096 + (off >> 3)] = make_uint2(bf2u(h01), bf2u(h23));
        g_Blo[m * 4096 + (off >> 3)] = make_uint2(bf2u(l01), bf2u(l23));
    }
}

// ---------------- fused edge scatter: all 3 relations in one launch ----------------
__global__ void __launch_bounds__(256) scatter_all(
    const float4* __restrict__ f0, const int* __restrict__ s0, const int* __restrict__ d0,
    const float* __restrict__ w0, float4* __restrict__ a0, float* __restrict__ dg0,
    const float4* __restrict__ f1, const int* __restrict__ s1, const int* __restrict__ d1,
    const float* __restrict__ w1, float4* __restrict__ a1, float* __restrict__ dg1,
    const float4* __restrict__ f2, const int* __restrict__ s2, const int* __restrict__ d2,
    const float* __restrict__ w2, float4* __restrict__ a2, float* __restrict__ dg2,
    int E, int wpr)
{
    int gw = (blockIdx.x * 256 + threadIdx.x) >> 5;
    int lane = threadIdx.x & 31;
    int rel = gw / wpr;
    if (rel >= 3) return;
    int e0 = (gw - rel * wpr) * 8;
    if (e0 >= E) return;
    int n = E - e0; if (n > 8) n = 8;

    const float4* feat; const int* src; const int* dst; const float* ew; float4* acc; float* deg;
    if (rel == 0)      { feat = f0; src = s0; dst = d0; ew = w0; acc = a0; deg = dg0; }
    else if (rel == 1) { feat = f1; src = s1; dst = d1; ew = w1; acc = a1; deg = dg1; }
    else               { feat = f2; src = s2; dst = d2; ew = w2; acc = a2; deg = dg2; }

    int s_ = 0, d_ = 0; float w_ = 0.f;
    if (lane < n) {
        s_ = __ldg(&src[e0 + lane]);
        d_ = __ldg(&dst[e0 + lane]);
        w_ = __ldg(&ew[e0 + lane]);
    }
    float4 v[8];
    #pragma unroll
    for (int i = 0; i < 8; i++) {
        int s = __shfl_sync(0xffffffffu, s_, i);
        if (i < n) v[i] = feat[(size_t)s * 32 + lane];
    }
    #pragma unroll
    for (int i = 0; i < 8; i++) {
        int d   = __shfl_sync(0xffffffffu, d_, i);
        float w = __shfl_sync(0xffffffffu, w_, i);
        if (i < n) {
            float4 t = v[i];
            t.x *= w; t.y *= w; t.z *= w; t.w *= w;
            red_add_v4((float*)(acc + (size_t)d * 32 + lane), t);
        }
    }
    if (lane < n) atomicAdd(deg + d_, 1.0f);
}

// ---------------- tensor-core GEMM via mma.sync (HMMA bf16, hi/lo split) ----------------
// C[M,128] = relu(sum_b scale_b(A_b) @ W_b + bias). 128x128 CTA tile, 8 warps (4x2),
// K staged in 64-wide halves (smem 66KB -> 2+ CTAs/SM), cp.async B copy overlaps A convert.
#define OFF_AHI   0
#define OFF_ALO   16384
#define OFF_BHI   32768
#define OFF_BLO   49152
#define OFF_BIAS  65536
#define GEMM_SMEM 66048

__global__ void __launch_bounds__(256, 2) gemm_tc(
    const float* __restrict__ A0, const float* __restrict__ dg0, const uint2* __restrict__ B0h, const uint2* __restrict__ B0l,
    const float* __restrict__ A1, const float* __restrict__ dg1, const uint2* __restrict__ B1h, const uint2* __restrict__ B1l,
    const float* __restrict__ A2, const float* __restrict__ dg2, const uint2* __restrict__ B2h, const uint2* __restrict__ B2l,
    const float* __restrict__ bias, float* __restrict__ C, int M, int nblk)
{
    extern __shared__ __align__(1024) char smem[];
    const uint32_t sb = smem_u32(smem);
    const int tid = threadIdx.x;
    const int wid = tid >> 5, lane = tid & 31;
    const int m0 = blockIdx.x * 128;
    const int mw = wid >> 1;     // 0..3 (M warp row)
    const int nw = wid & 1;      // 0..1 (N warp col)

    if (tid < 128) ((float*)(smem + OFF_BIAS))[tid] = bias[tid];

    float acc[2][8][4];
    #pragma unroll
    for (int i = 0; i < 2; i++)
        #pragma unroll
        for (int j = 0; j < 8; j++)
            #pragma unroll
            for (int q = 0; q < 4; q++) acc[i][j][q] = 0.f;

    const float* Ap[3] = {A0, A1, A2};
    const float* Dp[3] = {dg0, dg1, dg2};
    const uint2* Bh[3] = {B0h, B1h, B2h};
    const uint2* Bl[3] = {B0l, B1l, B2l};

    // per-lane fragment addressing constants
    const int a_rowl = lane & 15;         // row within m16 tile
    const int a_half = lane >> 4;         // k chunk half
    const int b_rowl = (lane & 7) + ((lane >> 4) << 3);  // row within n16 tile
    const int b_half = (lane >> 3) & 1;   // k chunk half

    // A staging indices: 2048 float4 per half / 256 thr = 8 each
    for (int blk = 0; blk < nblk; blk++) {
        const float* A = Ap[blk];
        const float* dgp = Dp[blk];
        #pragma unroll
        for (int kh = 0; kh < 2; kh++) {
            __syncthreads();
            // ---- B copy via cp.async (pre-swizzled, per-half contiguous) ----
            {
                const char* bh = (const char*)Bh[blk] + kh * 16384;
                const char* bl = (const char*)Bl[blk] + kh * 16384;
                #pragma unroll
                for (int i = 0; i < 4; i++) {
                    int t = (tid + i * 256) * 16;
                    cp_async16(sb + OFF_BHI + t, bh + t);
                    cp_async16(sb + OFF_BLO + t, bl + t);
                }
                asm volatile("cp.async.commit_group;" ::: "memory");
            }
            // ---- A convert: fp32 -> bf16 hi/lo, swizzled (overlaps B copy) ----
            #pragma unroll
            for (int j = 0; j < 8; j++) {
                int f = tid + j * 256;
                int row = f >> 4, cg = f & 15;     // 16 float4 per row-half
                int grow = m0 + row;
                float4 a = make_float4(0.f, 0.f, 0.f, 0.f);
                float sc = 1.f;
                if (grow < M) {
                    a = *(const float4*)(A + (size_t)grow * 128 + kh * 64 + cg * 4);
                    if (dgp) sc = 1.f / fmaxf(__ldg(&dgp[grow]), 1.f);
                }
                float x0 = a.x * sc, x1 = a.y * sc, x2 = a.z * sc, x3 = a.w * sc;
                __nv_bfloat162 h01 = __floats2bfloat162_rn(x0, x1);
                __nv_bfloat162 h23 = __floats2bfloat162_rn(x2, x3);
                float2 f01 = __bfloat1622float2(h01), f23 = __bfloat1622float2(h23);
                __nv_bfloat162 l01 = __floats2bfloat162_rn(x0 - f01.x, x1 - f01.y);
                __nv_bfloat162 l23 = __floats2bfloat162_rn(x2 - f23.x, x3 - f23.y);
                uint32_t off = swz_off(row, cg >> 1, (cg & 1) << 3);
                *(uint2*)(smem + OFF_AHI + off) = make_uint2(bf2u(h01), bf2u(h23));
                *(uint2*)(smem + OFF_ALO + off) = make_uint2(bf2u(l01), bf2u(l23));
            }
            asm volatile("cp.async.wait_group 0;" ::: "memory");
            __syncthreads();

            // ---- compute: 4 k16-steps per half ----
            #pragma unroll
            for (int ks = 0; ks < 4; ks++) {
                uint32_t ah[2][4], al[2][4];
                #pragma unroll
                for (int mt = 0; mt < 2; mt++) {
                    int r = mw * 32 + mt * 16 + a_rowl;
                    uint32_t off = swz_off(r, 2 * ks + a_half, 0);
                    ldsm_x4(ah[mt], sb + OFF_AHI + off);
                    ldsm_x4(al[mt], sb + OFF_ALO + off);
                }
                #pragma unroll
                for (int nb = 0; nb < 4; nb++) {
                    int r = nw * 64 + nb * 16 + b_rowl;
                    uint32_t off = swz_off(r, 2 * ks + b_half, 0);
                    uint32_t bh[4], bl[4];
                    ldsm_x4(bh, sb + OFF_BHI + off);
                    ldsm_x4(bl, sb + OFF_BLO + off);
                    #pragma unroll
                    for (int mt = 0; mt < 2; mt++) {
                        mma_bf16(acc[mt][nb * 2 + 0], ah[mt], bh[0], bh[1]);
                        mma_bf16(acc[mt][nb * 2 + 1], ah[mt], bh[2], bh[3]);
                        mma_bf16(acc[mt][nb * 2 + 0], ah[mt], bl[0], bl[1]);
                        mma_bf16(acc[mt][nb * 2 + 1], ah[mt], bl[2], bl[3]);
                        mma_bf16(acc[mt][nb * 2 + 0], al[mt], bh[0], bh[1]);
                        mma_bf16(acc[mt][nb * 2 + 1], al[mt], bh[2], bh[3]);
                    }
                }
            }
        }
    }

    // ---- epilogue: bias + relu + store ----
    const float* bias_s = (const float*)(smem + OFF_BIAS);
    #pragma unroll
    for (int mt = 0; mt < 2; mt++) {
        int r0 = m0 + mw * 32 + mt * 16 + (lane >> 2);
        #pragma unroll
        for (int nt = 0; nt < 8; nt++) {
            int col = nw * 64 + nt * 8 + (lane & 3) * 2;
            float b0 = bias_s[col], b1 = bias_s[col + 1];
            if (r0 < M) {
                float2 v;
                v.x = fmaxf(acc[mt][nt][0] + b0, 0.f);
                v.y = fmaxf(acc[mt][nt][1] + b1, 0.f);
                *(float2*)(C + (size_t)r0 * 128 + col) = v;
            }
            if (r0 + 8 < M) {
                float2 v;
                v.x = fmaxf(acc[mt][nt][2] + b0, 0.f);
                v.y = fmaxf(acc[mt][nt][3] + b1, 0.f);
                *(float2*)(C + (size_t)(r0 + 8) * 128 + col) = v;
            }
        }
    }
}

// ---------------- projection: P[M,NC] = H[M,128] @ W[128,NC]  (warp per row) ----------------
template <int NC>
__global__ void __launch_bounds__(256) proj_kernel(const float4* __restrict__ H,
                                                   const float* __restrict__ W,
                                                   float* __restrict__ P, int M)
{
    __shared__ float Ws[128 * NC];
    for (int i = threadIdx.x; i < 128 * NC; i += 256) Ws[i] = W[i];
    __syncthreads();
    int warp = (blockIdx.x * 256 + threadIdx.x) >> 5;
    int lane = threadIdx.x & 31;
    if (warp >= M) return;
    float4 h = H[(size_t)warp * 32 + lane];
    int k = lane * 4;
    float acc[NC];
    #pragma unroll
    for (int c = 0; c < NC; c++)
        acc[c] = h.x * Ws[(k + 0) * NC + c] + h.y * Ws[(k + 1) * NC + c]
               + h.z * Ws[(k + 2) * NC + c] + h.w * Ws[(k + 3) * NC + c];
    #pragma unroll
    for (int c = 0; c < NC; c++)
        #pragma unroll
        for (int o = 16; o > 0; o >>= 1) acc[c] += __shfl_xor_sync(0xffffffffu, acc[c], o);
    if (lane == 0) {
        #pragma unroll
        for (int c = 0; c < NC; c++) P[(size_t)warp * NC + c] = acc[c];
    }
}

// ---------------- 2-wide edge scatter on projected features ----------------
__global__ void __launch_bounds__(256) scatter_proj(
    const float* __restrict__ P, int stride, int off,
    const int* __restrict__ src, const int* __restrict__ dst, const float* __restrict__ ew,
    float* __restrict__ Q, int E)
{
    int e = blockIdx.x * 256 + threadIdx.x;
    if (e >= E) return;
    int s = src[e], d = dst[e];
    float w = ew[e];
    float a = P[(size_t)s * stride + off]     * w;
    float b = P[(size_t)s * stride + off + 1] * w;
    red_add_v2(Q + (size_t)d * 2, a, b);
}

// ---------------- finalize ----------------
__global__ void __launch_bounds__(256) finalize_kernel(float* __restrict__ out)
{
    int v = blockIdx.x * 256 + threadIdx.x;
    if (v >= N_APP) return;
    float i1 = 1.0f / fmaxf(g_deg1[v], 1.0f);
    float i2 = 1.0f / fmaxf(g_deg2[v], 1.0f);
    out[v * 2 + 0] = g_papp[v * 4 + 0] + g_q1[v * 2 + 0] * i1 + g_q2[v * 2 + 0] * i2 + g_bce[0];
    out[v * 2 + 1] = g_papp[v * 4 + 1] + g_q1[v * 2 + 1] * i1 + g_q2[v * 2 + 1] * i2 + g_bce[1];
}

// ---------------- launch ----------------
extern "C" void kernel_launch(void* const* d_in, const int* in_sizes, int n_in,
                              void* d_out, int out_size)
{
    const float* x_app   = (const float*)d_in[0];
    const float* x_attr  = (const float*)d_in[1];
    const float* ew0     = (const float*)d_in[2];
    const float* ew1     = (const float*)d_in[3];
    const float* ew2     = (const float*)d_in[4];
    const float* Wself1  = (const float*)d_in[5];
    const float* Wneigh1 = (const float*)d_in[6];
    const float* b1      = (const float*)d_in[7];
    const float* Wself2  = (const float*)d_in[8];
    const float* Wneigh2 = (const float*)d_in[9];
    const float* b2      = (const float*)d_in[10];
    const float* Wc      = (const float*)d_in[11];
    const float* bc      = (const float*)d_in[12];
    const int* src0 = (const int*)d_in[13];
    const int* dst0 = (const int*)d_in[14];
    const int* src1 = (const int*)d_in[15];
    const int* dst1 = (const int*)d_in[16];
    const int* src2 = (const int*)d_in[17];
    const int* dst2 = (const int*)d_in[18];
    float* out = (float*)d_out;
    const int E = in_sizes[2];

    float *n0, *n1, *n2, *hattr, *happ, *deg0, *deg1, *deg2, *pattr, *papp, *q1, *q2;
    float *bsum1, *Wn1c, *Wapp4;
    uint2 *Bhi, *Blo;
    cudaGetSymbolAddress((void**)&n0, g_n0);
    cudaGetSymbolAddress((void**)&n1, g_n1);
    cudaGetSymbolAddress((void**)&n2, g_n2);
    cudaGetSymbolAddress((void**)&hattr, g_hattr);
    cudaGetSymbolAddress((void**)&happ, g_happ);
    cudaGetSymbolAddress((void**)&deg0, g_deg0);
    cudaGetSymbolAddress((void**)&deg1, g_deg1);
    cudaGetSymbolAddress((void**)&deg2, g_deg2);
    cudaGetSymbolAddress((void**)&pattr, g_pattr);
    cudaGetSymbolAddress((void**)&papp, g_papp);
    cudaGetSymbolAddress((void**)&q1, g_q1);
    cudaGetSymbolAddress((void**)&q2, g_q2);
    cudaGetSymbolAddress((void**)&bsum1, g_bsum1);
    cudaGetSymbolAddress((void**)&Wn1c, g_Wn1c);
    cudaGetSymbolAddress((void**)&Wapp4, g_Wapp4);
    cudaGetSymbolAddress((void**)&Bhi, g_Bhi);
    cudaGetSymbolAddress((void**)&Blo, g_Blo);

    cudaFuncSetAttribute(gemm_tc, cudaFuncAttributeMaxDynamicSharedMemorySize, GEMM_SMEM);

    cudaMemsetAsync(n0, 0, sizeof(g_n0), 0);
    cudaMemsetAsync(n1, 0, sizeof(g_n1), 0);
    cudaMemsetAsync(n2, 0, sizeof(g_n2), 0);
    cudaMemsetAsync(deg0, 0, sizeof(g_deg0), 0);
    cudaMemsetAsync(deg1, 0, sizeof(g_deg1), 0);
    cudaMemsetAsync(deg2, 0, sizeof(g_deg2), 0);
    cudaMemsetAsync(q1, 0, sizeof(g_q1), 0);
    cudaMemsetAsync(q2, 0, sizeof(g_q2), 0);

    prep_kernel<<<1, 256>>>(b1, Wself2, Wneigh2, b2, Wc, bc);
    prep_weights<<<5, 256>>>(Wself1, Wneigh1);

    // fused layer-1 aggregation (3 relations, warp per 8 edges)
    int wpr = (E + 7) / 8;
    int sblocks = (3 * wpr * 32 + 255) / 256;
    scatter_all<<<sblocks, 256>>>(
        (const float4*)x_app,  src0, dst0, ew0, (float4*)n0, deg0,
        (const float4*)x_attr, src1, dst1, ew1, (float4*)n1, deg1,
        (const float4*)x_app,  src2, dst2, ew2, (float4*)n2, deg2,
        E, wpr);

    // layer-1 GEMMs on tensor cores (mma.sync bf16 hi/lo split)
    gemm_tc<<<(N_ATTR + 127) / 128, 256, GEMM_SMEM>>>(
        x_attr, nullptr, Bhi + 0 * 4096, Blo + 0 * 4096,
        n0, deg0,        Bhi + 1 * 4096, Blo + 1 * 4096,
        nullptr, nullptr, nullptr, nullptr,
        b1, hattr, N_ATTR, 2);
    gemm_tc<<<(N_APP + 127) / 128, 256, GEMM_SMEM>>>(
        x_app, nullptr, Bhi + 2 * 4096, Blo + 2 * 4096,
        n1, deg1,       Bhi + 3 * 4096, Blo + 3 * 4096,
        n2, deg2,       Bhi + 4 * 4096, Blo + 4 * 4096,
        bsum1, happ, N_APP, 3);

    // layer 2 folded to low-dim projections
    proj_kernel<2><<<(N_ATTR * 32 + 255) / 256, 256>>>((const float4*)hattr, Wn1c, pattr, N_ATTR);
    proj_kernel<4><<<(N_APP * 32 + 255) / 256, 256>>>((const float4*)happ, Wapp4, papp, N_APP);

    int eblocks = (E + 255) / 256;
    scatter_proj<<<eblocks, 256>>>(pattr, 2, 0, src1, dst1, ew1, q1, E);
    scatter_proj<<<eblocks, 256>>>(papp,  4, 2, src2, dst2, ew2, q2, E);

    finalize_kernel<<<(N_APP + 255) / 256, 256>>>(out);
}

// round 7
// speedup vs baseline: 1.6651x; 1.3271x over previous
#include <cuda_runtime.h>
#include <cuda_bf16.h>
#include <cstdint>

// Problem constants
#define N_APP  100000
#define N_ATTR 50000
#define D      128
#define NB_ATTR 391   // ceil(50000/128)
#define NB_APP  782   // ceil(100000/128)

// ---------------- device scratch (no allocation allowed) ----------------
__device__ float g_n0[(size_t)N_ATTR * D];
__device__ float g_n1[(size_t)N_APP * D];
__device__ float g_n2[(size_t)N_APP * D];
__device__ float g_deg0[N_ATTR];
__device__ float g_deg1[N_APP];
__device__ float g_deg2[N_APP];
__device__ float g_pattr[(size_t)N_ATTR * 2];
__device__ float g_papp[(size_t)N_APP * 4];
__device__ float g_q1[(size_t)N_APP * 2];
__device__ float g_q2[(size_t)N_APP * 2];
__device__ float g_bsum1[D];       // b1[1]+b1[2]
__device__ float g_Wn1c[D * 2];    // Wneigh2[1] @ Wc
__device__ float g_Wapp4[D * 4];   // cols 0..1: (Wself2[1]+Wself2[2])@Wc ; cols 2..3: Wneigh2[2]@Wc
__device__ float g_bce[2];         // (b2[1]+b2[2])@Wc + bc
// bf16 weight tiles, merged hi/lo row-local layout:
// tile m (0..4), half kh (0..1): 32KB block = 128 rows x 256B; row n: [hi 128B | lo 128B],
// hi chunk c (16B, k-local 8c..8c+7) at ((c ^ (n&7))<<4). tiles: 0=Wself1[0], 1=Wneigh1[0],
// 2=Wself1[1]+Wself1[2], 3=Wneigh1[1], 4=Wneigh1[2]
__device__ uint2 g_Bt[5 * 2 * 4096];

// ---------------- PTX helpers ----------------
__device__ __forceinline__ uint32_t smem_u32(const void* p) {
    uint32_t a;
    asm("{ .reg .u64 t; cvta.to.shared.u64 t, %1; cvt.u32.u64 %0, t; }" : "=r"(a) : "l"(p));
    return a;
}
__device__ __forceinline__ void ldsm_x4(uint32_t* r, uint32_t addr) {
    asm volatile("ldmatrix.sync.aligned.m8n8.x4.shared.b16 {%0,%1,%2,%3}, [%4];"
                 : "=r"(r[0]), "=r"(r[1]), "=r"(r[2]), "=r"(r[3]) : "r"(addr));
}
__device__ __forceinline__ void mma_bf16(float* c, const uint32_t* a, uint32_t b0, uint32_t b1) {
    asm volatile("mma.sync.aligned.m16n8k16.row.col.f32.bf16.bf16.f32 "
                 "{%0,%1,%2,%3}, {%4,%5,%6,%7}, {%8,%9}, {%0,%1,%2,%3};"
                 : "+f"(c[0]), "+f"(c[1]), "+f"(c[2]), "+f"(c[3])
                 : "r"(a[0]), "r"(a[1]), "r"(a[2]), "r"(a[3]), "r"(b0), "r"(b1));
}
__device__ __forceinline__ void cp_async16(uint32_t dst, const void* src) {
    asm volatile("cp.async.cg.shared.global [%0], [%1], 16;" :: "r"(dst), "l"(src) : "memory");
}
__device__ __forceinline__ void sts_u2(uint32_t addr, uint32_t a, uint32_t b) {
    asm volatile("st.shared.v2.b32 [%0], {%1,%2};" :: "r"(addr), "r"(a), "r"(b));
}
__device__ __forceinline__ void sts_zero16(uint32_t addr) {
    asm volatile("st.shared.v4.b32 [%0], {%1,%1,%1,%1};" :: "r"(addr), "r"(0u));
}
__device__ __forceinline__ float4 lds_f4(uint32_t addr) {
    float4 v;
    asm volatile("ld.shared.v4.f32 {%0,%1,%2,%3}, [%4];"
                 : "=f"(v.x), "=f"(v.y), "=f"(v.z), "=f"(v.w) : "r"(addr));
    return v;
}
__device__ __forceinline__ uint32_t bf2u(__nv_bfloat162 v) {
    return *reinterpret_cast<uint32_t*>(&v);
}

// ---------------- red helpers ----------------
__device__ __forceinline__ void red_add_v4(float* addr, float4 v) {
    asm volatile("red.global.add.v4.f32 [%0], {%1,%2,%3,%4};"
                 :: "l"(addr), "f"(v.x), "f"(v.y), "f"(v.z), "f"(v.w) : "memory");
}
__device__ __forceinline__ void red_add_v2(float* addr, float a, float b) {
    asm volatile("red.global.add.v2.f32 [%0], {%1,%2};"
                 :: "l"(addr), "f"(a), "f"(b) : "memory");
}

// ---------------- small-weight prep ----------------
__global__ void prep_kernel(const float* __restrict__ b1,
                            const float* __restrict__ Wself2, const float* __restrict__ Wneigh2,
                            const float* __restrict__ b2,
                            const float* __restrict__ Wc, const float* __restrict__ bc)
{
    int tid = threadIdx.x;
    if (tid < D) g_bsum1[tid] = b1[128 + tid] + b1[256 + tid];
    {
        int i = tid >> 1, j = tid & 1;
        float s_sc = 0.f, s_n2 = 0.f, s_n1 = 0.f;
        #pragma unroll 4
        for (int l = 0; l < D; l++) {
            float wc = Wc[l * 2 + j];
            s_sc += (Wself2[16384 + i * D + l] + Wself2[32768 + i * D + l]) * wc;
            s_n2 += Wneigh2[32768 + i * D + l] * wc;
            s_n1 += Wneigh2[16384 + i * D + l] * wc;
        }
        g_Wapp4[i * 4 + j]     = s_sc;
        g_Wapp4[i * 4 + 2 + j] = s_n2;
        g_Wn1c[i * 2 + j]      = s_n1;
    }
    if (tid < 2) {
        float s = bc[tid];
        for (int l = 0; l < D; l++) s += (b2[128 + l] + b2[256 + l]) * Wc[l * 2 + tid];
        g_bce[tid] = s;
    }
}

// ---------------- weight tiles: transpose + hi/lo bf16 split + merged row-local layout ----------------
__global__ void prep_weights(const float* __restrict__ Wself1, const float* __restrict__ Wneigh1)
{
    int m = blockIdx.x;              // tile id 0..4
    int tid = threadIdx.x;
    for (int idx = tid; idx < 4096; idx += 256) {
        int n = idx >> 5;            // output-channel row 0..127
        int cg = idx & 31;           // uint2 (4 bf16) group along full k=128
        int k0 = cg * 4;
        float w[4];
        #pragma unroll
        for (int i = 0; i < 4; i++) {
            int k = k0 + i;
            float v;
            if      (m == 0) v = Wself1[k * D + n];
            else if (m == 1) v = Wneigh1[k * D + n];
            else if (m == 2) v = Wself1[16384 + k * D + n] + Wself1[32768 + k * D + n];
            else if (m == 3) v = Wneigh1[16384 + k * D + n];
            else             v = Wneigh1[32768 + k * D + n];
            w[i] = v;
        }
        __nv_bfloat162 h01 = __floats2bfloat162_rn(w[0], w[1]);
        __nv_bfloat162 h23 = __floats2bfloat162_rn(w[2], w[3]);
        float2 f01 = __bfloat1622float2(h01), f23 = __bfloat1622float2(h23);
        __nv_bfloat162 l01 = __floats2bfloat162_rn(w[0] - f01.x, w[1] - f01.y);
        __nv_bfloat162 l23 = __floats2bfloat162_rn(w[2] - f23.x, w[3] - f23.y);
        int half = cg >> 4;
        int cgi  = cg & 15;
        char* base = (char*)g_Bt + ((size_t)(m * 2 + half)) * 32768 + (size_t)n * 256;
        uint32_t sw = (uint32_t)((((cgi >> 1) ^ (n & 7)) << 4) + ((cgi & 1) << 3));
        *(uint2*)(base + sw)       = make_uint2(bf2u(h01), bf2u(h23));
        *(uint2*)(base + 128 + sw) = make_uint2(bf2u(l01), bf2u(l23));
    }
}

// ---------------- fused edge scatter: all 3 relations in one launch ----------------
__global__ void __launch_bounds__(256) scatter_all(
    const float4* __restrict__ f0, const int* __restrict__ s0, const int* __restrict__ d0,
    const float* __restrict__ w0, float4* __restrict__ a0, float* __restrict__ dg0,
    const float4* __restrict__ f1, const int* __restrict__ s1, const int* __restrict__ d1,
    const float* __restrict__ w1, float4* __restrict__ a1, float* __restrict__ dg1,
    const float4* __restrict__ f2, const int* __restrict__ s2, const int* __restrict__ d2,
    const float* __restrict__ w2, float4* __restrict__ a2, float* __restrict__ dg2,
    int E, int wpr)
{
    int gw = (blockIdx.x * 256 + threadIdx.x) >> 5;
    int lane = threadIdx.x & 31;
    int rel = gw / wpr;
    if (rel >= 3) return;
    int e0 = (gw - rel * wpr) * 8;
    if (e0 >= E) return;
    int n = E - e0; if (n > 8) n = 8;

    const float4* feat; const int* src; const int* dst; const float* ew; float4* acc; float* deg;
    if (rel == 0)      { feat = f0; src = s0; dst = d0; ew = w0; acc = a0; deg = dg0; }
    else if (rel == 1) { feat = f1; src = s1; dst = d1; ew = w1; acc = a1; deg = dg1; }
    else               { feat = f2; src = s2; dst = d2; ew = w2; acc = a2; deg = dg2; }

    int s_ = 0, d_ = 0; float w_ = 0.f;
    if (lane < n) {
        s_ = __ldg(&src[e0 + lane]);
        d_ = __ldg(&dst[e0 + lane]);
        w_ = __ldg(&ew[e0 + lane]);
    }
    float4 v[8];
    #pragma unroll
    for (int i = 0; i < 8; i++) {
        int s = __shfl_sync(0xffffffffu, s_, i);
        if (i < n) v[i] = feat[(size_t)s * 32 + lane];
    }
    #pragma unroll
    for (int i = 0; i < 8; i++) {
        int d   = __shfl_sync(0xffffffffu, d_, i);
        float w = __shfl_sync(0xffffffffu, w_, i);
        if (i < n) {
            float4 t = v[i];
            t.x *= w; t.y *= w; t.z *= w; t.w *= w;
            red_add_v4((float*)(acc + (size_t)d * 32 + lane), t);
        }
    }
    if (lane < n) atomicAdd(deg + d_, 1.0f);
}

// ---------------- merged tensor-core GEMM + fused layer-2 projection ----------------
// Computes p = relu(sum_b scale_b(A_b) @ W_b + bias) @ Wproj, red.add into pattr/papp.
// cp.async pipelined A (raw fp32 staged, converted in place), merged hi/lo B tiles.
#define OFF_A0    0
#define OFF_A1    32768
#define OFF_B     65536
#define OFF_BIAS  98304
#define OFF_PW    98816
#define GEMM_SMEM 100864

__global__ void __launch_bounds__(256, 2) gemm_fused_all(
    const float* __restrict__ x_attr, const float* __restrict__ x_app,
    const float* __restrict__ n0, const float* __restrict__ deg0,
    const float* __restrict__ n1, const float* __restrict__ deg1,
    const float* __restrict__ n2, const float* __restrict__ deg2,
    const float* __restrict__ b1, const float* __restrict__ bsum1,
    const float* __restrict__ Wn1c, const float* __restrict__ Wapp4,
    const uint2* __restrict__ Bt,
    float* __restrict__ pattr, float* __restrict__ papp)
{
    extern __shared__ __align__(1024) char smem[];
    const uint32_t sb = smem_u32(smem);
    const int tid = threadIdx.x;
    const int wid = tid >> 5, lane = tid & 31;
    const int mw = wid >> 1;
    const int nw = wid & 1;

    const bool is_app = (int)blockIdx.x >= NB_ATTR;
    const int bid = is_app ? (int)blockIdx.x - NB_ATTR : (int)blockIdx.x;
    const int m0 = bid * 128;
    const int M = is_app ? N_APP : N_ATTR;
    const int nstg = is_app ? 6 : 4;

    const float* Ap[3]; const float* Dp[3]; int tile0;
    if (is_app) { Ap[0] = x_app;  Ap[1] = n1; Ap[2] = n2;
                  Dp[0] = nullptr; Dp[1] = deg1; Dp[2] = deg2; tile0 = 2; }
    else        { Ap[0] = x_attr; Ap[1] = n0; Ap[2] = nullptr;
                  Dp[0] = nullptr; Dp[1] = deg0; Dp[2] = nullptr; tile0 = 0; }
    const float* bias = is_app ? bsum1 : b1;

    // stage bias + proj weights into smem (first use is long after several barriers)
    if (tid < 128) ((float*)(smem + OFF_BIAS))[tid] = bias[tid];
    for (int idx = tid; idx < 512; idx += 256) {
        int r = idx >> 2, c = idx & 3;
        ((float*)(smem + OFF_PW))[idx] = is_app ? Wapp4[idx] : (c < 2 ? Wn1c[r * 2 + c] : 0.f);
    }

    float acc[2][8][4];
    #pragma unroll
    for (int i = 0; i < 2; i++)
        #pragma unroll
        for (int j = 0; j < 8; j++)
            #pragma unroll
            for (int q = 0; q < 4; q++) acc[i][j][q] = 0.f;

    const int a_rowl = lane & 15;
    const int a_half = lane >> 4;
    const int b_rowl = (lane & 7) + ((lane >> 4) << 3);
    const int b_half = (lane >> 3) & 1;

    const uint32_t bufA[2] = { sb + OFF_A0, sb + OFF_A1 };

    // ---- A prefetch: raw fp32, 16B granules; granule g=(row<<4)+cg at buf+g*16 ----
    auto prefetchA = [&](int s, uint32_t buf) {
        int blk = s >> 1, kh = s & 1;
        const float* A = Ap[blk];
        #pragma unroll
        for (int i = 0; i < 8; i++) {
            int g = tid + i * 256;
            int r = g >> 4, cg = g & 15;
            int grow = m0 + r;
            uint32_t dst = buf + (uint32_t)g * 16u;
            if (grow < M) cp_async16(dst, A + (size_t)grow * 128 + kh * 64 + cg * 4);
            else          sts_zero16(dst);
        }
        asm volatile("cp.async.commit_group;" ::: "memory");
    };

    // prologue
    prefetchA(0, bufA[0]);

    for (int s = 0; s < nstg; s++) {
        const int p = s & 1;
        __syncthreads();                       // previous compute done; B buffer free
        // ---- B copy (merged hi/lo 32KB block) ----
        {
            int blk = s >> 1, kh = s & 1;
            const char* bsrc = (const char*)Bt + ((size_t)(tile0 + blk) * 2 + kh) * 32768;
            #pragma unroll
            for (int i = 0; i < 8; i++) {
                uint32_t t = (uint32_t)(tid + i * 256) * 16u;
                cp_async16(sb + OFF_B + t, bsrc + t);
            }
            asm volatile("cp.async.commit_group;" ::: "memory");
        }
        asm volatile("cp.async.wait_group 1;" ::: "memory");   // A(s) landed (own-thread data)
        // ---- in-place convert: raw fp32 -> [hi 128B | lo 128B] per 256B row slot ----
        {
            int blk = s >> 1;
            const float* dgp = Dp[blk];
            #pragma unroll
            for (int h = 0; h < 2; h++) {       // disjoint row halves (rows 0-63 / 64-127)
                float4 raw[4]; float scs[4];
                #pragma unroll
                for (int i = 0; i < 4; i++) {
                    int g = h * 1024 + tid + i * 256;
                    raw[i] = lds_f4(bufA[p] + (uint32_t)g * 16u);
                    int grow = m0 + (g >> 4);
                    scs[i] = 1.f;
                    if (dgp != nullptr && grow < M) scs[i] = 1.f / fmaxf(__ldg(&dgp[grow]), 1.f);
                }
                __syncthreads();
                #pragma unroll
                for (int i = 0; i < 4; i++) {
                    int g = h * 1024 + tid + i * 256;
                    int r = g >> 4, cg = g & 15;
                    float x0 = raw[i].x * scs[i], x1 = raw[i].y * scs[i];
                    float x2 = raw[i].z * scs[i], x3 = raw[i].w * scs[i];
                    __nv_bfloat162 h01 = __floats2bfloat162_rn(x0, x1);
                    __nv_bfloat162 h23 = __floats2bfloat162_rn(x2, x3);
                    float2 f01 = __bfloat1622float2(h01), f23 = __bfloat1622float2(h23);
                    __nv_bfloat162 l01 = __floats2bfloat162_rn(x0 - f01.x, x1 - f01.y);
                    __nv_bfloat162 l23 = __floats2bfloat162_rn(x2 - f23.x, x3 - f23.y);
                    uint32_t base = bufA[p] + (uint32_t)r * 256u
                                  + (uint32_t)((((cg >> 1) ^ (r & 7)) << 4) + ((cg & 1) << 3));
                    sts_u2(base,        bf2u(h01), bf2u(h23));
                    sts_u2(base + 128u, bf2u(l01), bf2u(l23));
                }
                __syncthreads();
            }
        }
        asm volatile("cp.async.wait_group 0;" ::: "memory");   // B(s) landed
        __syncthreads();                                       // B + converted A visible
        if (s + 1 < nstg) prefetchA(s + 1, bufA[1 - p]);       // hide next A behind compute

        // ---- compute: 4 k16-steps ----
        #pragma unroll
        for (int ks = 0; ks < 4; ks++) {
            uint32_t ah[2][4], al[2][4];
            #pragma unroll
            for (int mt = 0; mt < 2; mt++) {
                int r = mw * 32 + mt * 16 + a_rowl;
                uint32_t base = bufA[p] + (uint32_t)r * 256u
                              + (uint32_t)(((2 * ks + a_half) ^ (r & 7)) << 4);
                ldsm_x4(ah[mt], base);
                ldsm_x4(al[mt], base + 128u);
            }
            #pragma unroll
            for (int nb = 0; nb < 4; nb++) {
                int r = nw * 64 + nb * 16 + b_rowl;
                uint32_t base = sb + OFF_B + (uint32_t)r * 256u
                              + (uint32_t)(((2 * ks + b_half) ^ (r & 7)) << 4);
                uint32_t bh[4], bl[4];
                ldsm_x4(bh, base);
                ldsm_x4(bl, base + 128u);
                #pragma unroll
                for (int mt = 0; mt < 2; mt++) {
                    mma_bf16(acc[mt][nb * 2 + 0], ah[mt], bh[0], bh[1]);
                    mma_bf16(acc[mt][nb * 2 + 1], ah[mt], bh[2], bh[3]);
                    mma_bf16(acc[mt][nb * 2 + 0], ah[mt], bl[0], bl[1]);
                    mma_bf16(acc[mt][nb * 2 + 1], ah[mt], bl[2], bl[3]);
                    mma_bf16(acc[mt][nb * 2 + 0], al[mt], bh[0], bh[1]);
                    mma_bf16(acc[mt][nb * 2 + 1], al[mt], bh[2], bh[3]);
                }
            }
        }
    }

    // ---- epilogue: relu(acc+bias) @ Wproj, shfl-reduce, red.add to pattr/papp ----
    const float* bias_s = (const float*)(smem + OFF_BIAS);
    const float* pw = (const float*)(smem + OFF_PW);
    #pragma unroll
    for (int mt = 0; mt < 2; mt++) {
        float p0[4] = {0.f, 0.f, 0.f, 0.f};
        float p1[4] = {0.f, 0.f, 0.f, 0.f};
        #pragma unroll
        for (int nt = 0; nt < 8; nt++) {
            int col = nw * 64 + nt * 8 + (lane & 3) * 2;
            float b0 = bias_s[col], b1v = bias_s[col + 1];
            float vx = fmaxf(acc[mt][nt][0] + b0, 0.f);
            float vy = fmaxf(acc[mt][nt][1] + b1v, 0.f);
            float vz = fmaxf(acc[mt][nt][2] + b0, 0.f);
            float vw = fmaxf(acc[mt][nt][3] + b1v, 0.f);
            #pragma unroll
            for (int c = 0; c < 4; c++) {
                p0[c] += vx * pw[col * 4 + c] + vy * pw[(col + 1) * 4 + c];
                p1[c] += vz * pw[col * 4 + c] + vw * pw[(col + 1) * 4 + c];
            }
        }
        #pragma unroll
        for (int c = 0; c < 4; c++) {
            p0[c] += __shfl_xor_sync(0xffffffffu, p0[c], 1);
            p0[c] += __shfl_xor_sync(0xffffffffu, p0[c], 2);
            p1[c] += __shfl_xor_sync(0xffffffffu, p1[c], 1);
            p1[c] += __shfl_xor_sync(0xffffffffu, p1[c], 2);
        }
        if ((lane & 3) == 0) {
            int r0 = m0 + mw * 32 + mt * 16 + (lane >> 2);
            if (is_app) {
                if (r0 < M)     red_add_v4(papp + (size_t)r0 * 4, make_float4(p0[0], p0[1], p0[2], p0[3]));
                if (r0 + 8 < M) red_add_v4(papp + (size_t)(r0 + 8) * 4, make_float4(p1[0], p1[1], p1[2], p1[3]));
            } else {
                if (r0 < M)     red_add_v2(pattr + (size_t)r0 * 2, p0[0], p0[1]);
                if (r0 + 8 < M) red_add_v2(pattr + (size_t)(r0 + 8) * 2, p1[0], p1[1]);
            }
        }
    }
}

// ---------------- 2-wide edge scatter on projected features ----------------
__global__ void __launch_bounds__(256) scatter_proj(
    const float* __restrict__ P, int stride, int off,
    const int* __restrict__ src, const int* __restrict__ dst, const float* __restrict__ ew,
    float* __restrict__ Q, int E)
{
    int e = blockIdx.x * 256 + threadIdx.x;
    if (e >= E) return;
    int s = src[e], d = dst[e];
    float w = ew[e];
    float a = P[(size_t)s * stride + off]     * w;
    float b = P[(size_t)s * stride + off + 1] * w;
    red_add_v2(Q + (size_t)d * 2, a, b);
}

// ---------------- finalize ----------------
__global__ void __launch_bounds__(256) finalize_kernel(float* __restrict__ out)
{
    int v = blockIdx.x * 256 + threadIdx.x;
    if (v >= N_APP) return;
    float i1 = 1.0f / fmaxf(g_deg1[v], 1.0f);
    float i2 = 1.0f / fmaxf(g_deg2[v], 1.0f);
    out[v * 2 + 0] = g_papp[v * 4 + 0] + g_q1[v * 2 + 0] * i1 + g_q2[v * 2 + 0] * i2 + g_bce[0];
    out[v * 2 + 1] = g_papp[v * 4 + 1] + g_q1[v * 2 + 1] * i1 + g_q2[v * 2 + 1] * i2 + g_bce[1];
}

// ---------------- launch ----------------
extern "C" void kernel_launch(void* const* d_in, const int* in_sizes, int n_in,
                              void* d_out, int out_size)
{
    const float* x_app   = (const float*)d_in[0];
    const float* x_attr  = (const float*)d_in[1];
    const float* ew0     = (const float*)d_in[2];
    const float* ew1     = (const float*)d_in[3];
    const float* ew2     = (const float*)d_in[4];
    const float* Wself1  = (const float*)d_in[5];
    const float* Wneigh1 = (const float*)d_in[6];
    const float* b1      = (const float*)d_in[7];
    const float* Wself2  = (const float*)d_in[8];
    const float* Wneigh2 = (const float*)d_in[9];
    const float* b2      = (const float*)d_in[10];
    const float* Wc      = (const float*)d_in[11];
    const float* bc      = (const float*)d_in[12];
    const int* src0 = (const int*)d_in[13];
    const int* dst0 = (const int*)d_in[14];
    const int* src1 = (const int*)d_in[15];
    const int* dst1 = (const int*)d_in[16];
    const int* src2 = (const int*)d_in[17];
    const int* dst2 = (const int*)d_in[18];
    float* out = (float*)d_out;
    const int E = in_sizes[2];

    float *n0, *n1, *n2, *deg0, *deg1, *deg2, *pattr, *papp, *q1, *q2;
    float *bsum1, *Wn1c, *Wapp4;
    uint2 *Bt;
    cudaGetSymbolAddress((void**)&n0, g_n0);
    cudaGetSymbolAddress((void**)&n1, g_n1);
    cudaGetSymbolAddress((void**)&n2, g_n2);
    cudaGetSymbolAddress((void**)&deg0, g_deg0);
    cudaGetSymbolAddress((void**)&deg1, g_deg1);
    cudaGetSymbolAddress((void**)&deg2, g_deg2);
    cudaGetSymbolAddress((void**)&pattr, g_pattr);
    cudaGetSymbolAddress((void**)&papp, g_papp);
    cudaGetSymbolAddress((void**)&q1, g_q1);
    cudaGetSymbolAddress((void**)&q2, g_q2);
    cudaGetSymbolAddress((void**)&bsum1, g_bsum1);
    cudaGetSymbolAddress((void**)&Wn1c, g_Wn1c);
    cudaGetSymbolAddress((void**)&Wapp4, g_Wapp4);
    cudaGetSymbolAddress((void**)&Bt, g_Bt);

    cudaFuncSetAttribute(gemm_fused_all, cudaFuncAttributeMaxDynamicSharedMemorySize, GEMM_SMEM);

    cudaMemsetAsync(n0, 0, sizeof(g_n0), 0);
    cudaMemsetAsync(n1, 0, sizeof(g_n1), 0);
    cudaMemsetAsync(n2, 0, sizeof(g_n2), 0);
    cudaMemsetAsync(deg0, 0, sizeof(g_deg0), 0);
    cudaMemsetAsync(deg1, 0, sizeof(g_deg1), 0);
    cudaMemsetAsync(deg2, 0, sizeof(g_deg2), 0);
    cudaMemsetAsync(q1, 0, sizeof(g_q1), 0);
    cudaMemsetAsync(q2, 0, sizeof(g_q2), 0);
    cudaMemsetAsync(pattr, 0, sizeof(g_pattr), 0);
    cudaMemsetAsync(papp, 0, sizeof(g_papp), 0);

    prep_kernel<<<1, 256>>>(b1, Wself2, Wneigh2, b2, Wc, bc);
    prep_weights<<<5, 256>>>(Wself1, Wneigh1);

    // fused layer-1 aggregation (3 relations, warp per 8 edges)
    int wpr = (E + 7) / 8;
    int sblocks = (3 * wpr * 32 + 255) / 256;
    scatter_all<<<sblocks, 256>>>(
        (const float4*)x_app,  src0, dst0, ew0, (float4*)n0, deg0,
        (const float4*)x_attr, src1, dst1, ew1, (float4*)n1, deg1,
        (const float4*)x_app,  src2, dst2, ew2, (float4*)n2, deg2,
        E, wpr);

    // merged layer-1 GEMMs + fused layer-2 projection (attr blocks then app blocks)
    gemm_fused_all<<<NB_ATTR + NB_APP, 256, GEMM_SMEM>>>(
        x_attr, x_app, n0, deg0, n1, deg1, n2, deg2,
        b1, bsum1, Wn1c, Wapp4, Bt, pattr, papp);

    // layer-2 aggregation on projected features
    int eblocks = (E + 255) / 256;
    scatter_proj<<<eblocks, 256>>>(pattr, 2, 0, src1, dst1, ew1, q1, E);
    scatter_proj<<<eblocks, 256>>>(papp,  4, 2, src2, dst2, ew2, q2, E);

    finalize_kernel<<<(N_APP + 255) / 256, 256>>>(out);
}

// round 8
// speedup vs baseline: 1.7020x; 1.0222x over previous
#include <cuda_runtime.h>
#include <cuda_bf16.h>
#include <cstdint>

// Problem constants
#define N_APP  100000
#define N_ATTR 50000
#define D      128
#define NB_ATTR 391   // ceil(50000/128)
#define NB_APP  782   // ceil(100000/128)
#define N_TOT  250000 // concatenated node space: [attr(rel0) | app(rel1) | app(rel2)]
#define BASE1  50000
#define BASE2  150000
#define EMAX   500000
#define NBLK_SCAN 245 // ceil(250000/1024)

// ---------------- device scratch (no allocation allowed) ----------------
__device__ float g_n0[(size_t)N_ATTR * D];
__device__ float g_n1[(size_t)N_APP * D];
__device__ float g_n2[(size_t)N_APP * D];
__device__ float g_pattr[(size_t)N_ATTR * 2];
__device__ float g_papp[(size_t)N_APP * 4];
__device__ float g_degF[N_TOT];
__device__ int   g_cnt[N_TOT];
__device__ int   g_row[N_TOT];
__device__ int   g_cur[N_TOT];
__device__ int   g_bsum[256];
__device__ int   g_eid[3 * EMAX];
__device__ float g_bsum1[D];       // b1[1]+b1[2]
__device__ float g_Wn1c[D * 2];    // Wneigh2[1] @ Wc
__device__ float g_Wapp4[D * 4];   // cols 0..1: (Wself2[1]+Wself2[2])@Wc ; cols 2..3: Wneigh2[2]@Wc
__device__ float g_bce[2];         // (b2[1]+b2[2])@Wc + bc
// bf16 weight tiles, merged hi/lo row-local layout (see prep_weights)
__device__ uint2 g_Bt[5 * 2 * 4096];

// ---------------- PTX helpers ----------------
__device__ __forceinline__ uint32_t smem_u32(const void* p) {
    uint32_t a;
    asm("{ .reg .u64 t; cvta.to.shared.u64 t, %1; cvt.u32.u64 %0, t; }" : "=r"(a) : "l"(p));
    return a;
}
__device__ __forceinline__ void ldsm_x4(uint32_t* r, uint32_t addr) {
    asm volatile("ldmatrix.sync.aligned.m8n8.x4.shared.b16 {%0,%1,%2,%3}, [%4];"
                 : "=r"(r[0]), "=r"(r[1]), "=r"(r[2]), "=r"(r[3]) : "r"(addr));
}
__device__ __forceinline__ void mma_bf16(float* c, const uint32_t* a, uint32_t b0, uint32_t b1) {
    asm volatile("mma.sync.aligned.m16n8k16.row.col.f32.bf16.bf16.f32 "
                 "{%0,%1,%2,%3}, {%4,%5,%6,%7}, {%8,%9}, {%0,%1,%2,%3};"
                 : "+f"(c[0]), "+f"(c[1]), "+f"(c[2]), "+f"(c[3])
                 : "r"(a[0]), "r"(a[1]), "r"(a[2]), "r"(a[3]), "r"(b0), "r"(b1));
}
__device__ __forceinline__ void cp_async16(uint32_t dst, const void* src) {
    asm volatile("cp.async.cg.shared.global [%0], [%1], 16;" :: "r"(dst), "l"(src) : "memory");
}
__device__ __forceinline__ void sts_u2(uint32_t addr, uint32_t a, uint32_t b) {
    asm volatile("st.shared.v2.b32 [%0], {%1,%2};" :: "r"(addr), "r"(a), "r"(b));
}
__device__ __forceinline__ void sts_zero16(uint32_t addr) {
    asm volatile("st.shared.v4.b32 [%0], {%1,%1,%1,%1};" :: "r"(addr), "r"(0u));
}
__device__ __forceinline__ float4 lds_f4(uint32_t addr) {
    float4 v;
    asm volatile("ld.shared.v4.f32 {%0,%1,%2,%3}, [%4];"
                 : "=f"(v.x), "=f"(v.y), "=f"(v.z), "=f"(v.w) : "r"(addr));
    return v;
}
__device__ __forceinline__ uint32_t bf2u(__nv_bfloat162 v) {
    return *reinterpret_cast<uint32_t*>(&v);
}
__device__ __forceinline__ void red_add_v4(float* addr, float4 v) {
    asm volatile("red.global.add.v4.f32 [%0], {%1,%2,%3,%4};"
                 :: "l"(addr), "f"(v.x), "f"(v.y), "f"(v.z), "f"(v.w) : "memory");
}
__device__ __forceinline__ void red_add_v2(float* addr, float a, float b) {
    asm volatile("red.global.add.v2.f32 [%0], {%1,%2};"
                 :: "l"(addr), "f"(a), "f"(b) : "memory");
}

// ---------------- small-weight prep ----------------
__global__ void prep_kernel(const float* __restrict__ b1,
                            const float* __restrict__ Wself2, const float* __restrict__ Wneigh2,
                            const float* __restrict__ b2,
                            const float* __restrict__ Wc, const float* __restrict__ bc)
{
    int tid = threadIdx.x;
    if (tid < D) g_bsum1[tid] = b1[128 + tid] + b1[256 + tid];
    {
        int i = tid >> 1, j = tid & 1;
        float s_sc = 0.f, s_n2 = 0.f, s_n1 = 0.f;
        #pragma unroll 4
        for (int l = 0; l < D; l++) {
            float wc = Wc[l * 2 + j];
            s_sc += (Wself2[16384 + i * D + l] + Wself2[32768 + i * D + l]) * wc;
            s_n2 += Wneigh2[32768 + i * D + l] * wc;
            s_n1 += Wneigh2[16384 + i * D + l] * wc;
        }
        g_Wapp4[i * 4 + j]     = s_sc;
        g_Wapp4[i * 4 + 2 + j] = s_n2;
        g_Wn1c[i * 2 + j]      = s_n1;
    }
    if (tid < 2) {
        float s = bc[tid];
        for (int l = 0; l < D; l++) s += (b2[128 + l] + b2[256 + l]) * Wc[l * 2 + tid];
        g_bce[tid] = s;
    }
}

// ---------------- weight tiles: transpose + hi/lo bf16 split + merged row-local layout ----------------
__global__ void prep_weights(const float* __restrict__ Wself1, const float* __restrict__ Wneigh1)
{
    int m = blockIdx.x;
    int tid = threadIdx.x;
    for (int idx = tid; idx < 4096; idx += 256) {
        int n = idx >> 5;
        int cg = idx & 31;
        int k0 = cg * 4;
        float w[4];
        #pragma unroll
        for (int i = 0; i < 4; i++) {
            int k = k0 + i;
            float v;
            if      (m == 0) v = Wself1[k * D + n];
            else if (m == 1) v = Wneigh1[k * D + n];
            else if (m == 2) v = Wself1[16384 + k * D + n] + Wself1[32768 + k * D + n];
            else if (m == 3) v = Wneigh1[16384 + k * D + n];
            else             v = Wneigh1[32768 + k * D + n];
            w[i] = v;
        }
        __nv_bfloat162 h01 = __floats2bfloat162_rn(w[0], w[1]);
        __nv_bfloat162 h23 = __floats2bfloat162_rn(w[2], w[3]);
        float2 f01 = __bfloat1622float2(h01), f23 = __bfloat1622float2(h23);
        __nv_bfloat162 l01 = __floats2bfloat162_rn(w[0] - f01.x, w[1] - f01.y);
        __nv_bfloat162 l23 = __floats2bfloat162_rn(w[2] - f23.x, w[3] - f23.y);
        int half = cg >> 4;
        int cgi  = cg & 15;
        char* base = (char*)g_Bt + ((size_t)(m * 2 + half)) * 32768 + (size_t)n * 256;
        uint32_t sw = (uint32_t)((((cgi >> 1) ^ (n & 7)) << 4) + ((cgi & 1) << 3));
        *(uint2*)(base + sw)       = make_uint2(bf2u(h01), bf2u(h23));
        *(uint2*)(base + 128 + sw) = make_uint2(bf2u(l01), bf2u(l23));
    }
}

// ---------------- CSR build: count -> scan -> fill ----------------
__global__ void count_kernel(const int* __restrict__ d0, const int* __restrict__ d1,
                             const int* __restrict__ d2, int E)
{
    int i = blockIdx.x * 256 + threadIdx.x;
    if (i < E)           atomicAdd(&g_cnt[d0[i]], 1);
    else if (i < 2 * E)  atomicAdd(&g_cnt[BASE1 + d1[i - E]], 1);
    else if (i < 3 * E)  atomicAdd(&g_cnt[BASE2 + d2[i - 2 * E]], 1);
}

__global__ void scan1_kernel()
{
    __shared__ int sh[8];
    int b = blockIdx.x, t = threadIdx.x;
    int base = b * 1024 + t * 4;
    int v[4];
    #pragma unroll
    for (int i = 0; i < 4; i++) v[i] = (base + i < N_TOT) ? g_cnt[base + i] : 0;
    int local = v[0] + v[1] + v[2] + v[3];
    int lane = t & 31, w = t >> 5;
    int inc = local;
    #pragma unroll
    for (int o = 1; o < 32; o <<= 1) {
        int x = __shfl_up_sync(0xffffffffu, inc, o);
        if (lane >= o) inc += x;
    }
    if (lane == 31) sh[w] = inc;
    __syncthreads();
    if (t == 0) {
        int run = 0;
        #pragma unroll
        for (int i = 0; i < 8; i++) { int x = sh[i]; sh[i] = run; run += x; }
        g_bsum[b] = run;
    }
    __syncthreads();
    int run = sh[w] + inc - local;
    #pragma unroll
    for (int i = 0; i < 4; i++) {
        if (base + i < N_TOT) g_row[base + i] = run;
        run += v[i];
    }
}

__global__ void scan2_kernel()
{
    __shared__ int sh[8];
    int t = threadIdx.x;
    int v = (t < NBLK_SCAN) ? g_bsum[t] : 0;
    int lane = t & 31, w = t >> 5;
    int inc = v;
    #pragma unroll
    for (int o = 1; o < 32; o <<= 1) {
        int x = __shfl_up_sync(0xffffffffu, inc, o);
        if (lane >= o) inc += x;
    }
    if (lane == 31) sh[w] = inc;
    __syncthreads();
    if (t == 0) {
        int run = 0;
        #pragma unroll
        for (int i = 0; i < 8; i++) { int x = sh[i]; sh[i] = run; run += x; }
    }
    __syncthreads();
    int excl = sh[w] + inc - v;
    if (t < NBLK_SCAN) g_bsum[t] = excl;
}

__global__ void scan3_kernel()
{
    int i = blockIdx.x * 256 + threadIdx.x;
    if (i >= N_TOT) return;
    int r = g_row[i] + g_bsum[i >> 10];
    g_row[i] = r;
    g_cur[i] = r;
    g_degF[i] = (float)g_cnt[i];
}

__global__ void fill_kernel(const int* __restrict__ d0, const int* __restrict__ d1,
                            const int* __restrict__ d2, int E)
{
    int i = blockIdx.x * 256 + threadIdx.x;
    int gidx, e;
    if (i < E)          { gidx = d0[i];              e = i; }
    else if (i < 2 * E) { e = i - E;     gidx = BASE1 + d1[e]; }
    else if (i < 3 * E) { e = i - 2 * E; gidx = BASE2 + d2[e]; }
    else return;
    int pos = atomicAdd(&g_cur[gidx], 1);
    g_eid[pos] = e;
}

// ---------------- CSR aggregation: warp per (relation, node), single write ----------------
__global__ void __launch_bounds__(256) agg_kernel(
    const float4* __restrict__ x_app, const float4* __restrict__ x_attr,
    const int* __restrict__ src0, const int* __restrict__ src1, const int* __restrict__ src2,
    const float* __restrict__ ew0, const float* __restrict__ ew1, const float* __restrict__ ew2)
{
    int gw = (blockIdx.x * 256 + threadIdx.x) >> 5;
    int lane = threadIdx.x & 31;
    if (gw >= N_TOT) return;
    const float4* feat; const int* src; const float* ew; float4* out; int v;
    if (gw < BASE1)      { feat = x_app;  src = src0; ew = ew0; out = (float4*)g_n0; v = gw; }
    else if (gw < BASE2) { feat = x_attr; src = src1; ew = ew1; out = (float4*)g_n1; v = gw - BASE1; }
    else                 { feat = x_app;  src = src2; ew = ew2; out = (float4*)g_n2; v = gw - BASE2; }
    int start = g_row[gw], n = g_cnt[gw];
    float4 acc = make_float4(0.f, 0.f, 0.f, 0.f);
    for (int c = 0; c < n; c += 32) {
        int m = n - c; if (m > 32) m = 32;
        int s = 0; float w = 0.f;
        if (lane < m) {
            int e = g_eid[start + c + lane];
            s = __ldg(&src[e]);
            w = __ldg(&ew[e]);
        }
        #pragma unroll 4
        for (int j = 0; j < m; j++) {
            int sj   = __shfl_sync(0xffffffffu, s, j);
            float wj = __shfl_sync(0xffffffffu, w, j);
            float4 t = feat[(size_t)sj * 32 + lane];
            acc.x += wj * t.x; acc.y += wj * t.y; acc.z += wj * t.z; acc.w += wj * t.w;
        }
    }
    out[(size_t)v * 32 + lane] = acc;
}

// ---------------- merged tensor-core GEMM + fused layer-2 projection ----------------
#define OFF_A0    0
#define OFF_A1    32768
#define OFF_B     65536
#define OFF_BIAS  98304
#define OFF_PW    98816
#define GEMM_SMEM 100864

__global__ void __launch_bounds__(256, 2) gemm_fused_all(
    const float* __restrict__ x_attr, const float* __restrict__ x_app,
    const float* __restrict__ n0, const float* __restrict__ deg0,
    const float* __restrict__ n1, const float* __restrict__ deg1,
    const float* __restrict__ n2, const float* __restrict__ deg2,
    const float* __restrict__ b1, const float* __restrict__ bsum1,
    const float* __restrict__ Wn1c, const float* __restrict__ Wapp4,
    const uint2* __restrict__ Bt,
    float* __restrict__ pattr, float* __restrict__ papp)
{
    extern __shared__ __align__(1024) char smem[];
    const uint32_t sb = smem_u32(smem);
    const int tid = threadIdx.x;
    const int wid = tid >> 5, lane = tid & 31;
    const int mw = wid >> 1;
    const int nw = wid & 1;

    const bool is_app = (int)blockIdx.x >= NB_ATTR;
    const int bid = is_app ? (int)blockIdx.x - NB_ATTR : (int)blockIdx.x;
    const int m0 = bid * 128;
    const int M = is_app ? N_APP : N_ATTR;
    const int nstg = is_app ? 6 : 4;

    const float* Ap[3]; const float* Dp[3]; int tile0;
    if (is_app) { Ap[0] = x_app;  Ap[1] = n1; Ap[2] = n2;
                  Dp[0] = nullptr; Dp[1] = deg1; Dp[2] = deg2; tile0 = 2; }
    else        { Ap[0] = x_attr; Ap[1] = n0; Ap[2] = nullptr;
                  Dp[0] = nullptr; Dp[1] = deg0; Dp[2] = nullptr; tile0 = 0; }
    const float* bias = is_app ? bsum1 : b1;

    if (tid < 128) ((float*)(smem + OFF_BIAS))[tid] = bias[tid];
    for (int idx = tid; idx < 512; idx += 256) {
        int r = idx >> 2, c = idx & 3;
        ((float*)(smem + OFF_PW))[idx] = is_app ? Wapp4[idx] : (c < 2 ? Wn1c[r * 2 + c] : 0.f);
    }

    float acc[2][8][4];
    #pragma unroll
    for (int i = 0; i < 2; i++)
        #pragma unroll
        for (int j = 0; j < 8; j++)
            #pragma unroll
            for (int q = 0; q < 4; q++) acc[i][j][q] = 0.f;

    const int a_rowl = lane & 15;
    const int a_half = lane >> 4;
    const int b_rowl = (lane & 7) + ((lane >> 4) << 3);
    const int b_half = (lane >> 3) & 1;

    const uint32_t bufA[2] = { sb + OFF_A0, sb + OFF_A1 };

    auto prefetchA = [&](int s, uint32_t buf) {
        int blk = s >> 1, kh = s & 1;
        const float* A = Ap[blk];
        #pragma unroll
        for (int i = 0; i < 8; i++) {
            int g = tid + i * 256;
            int r = g >> 4, cg = g & 15;
            int grow = m0 + r;
            uint32_t dst = buf + (uint32_t)g * 16u;
            if (grow < M) cp_async16(dst, A + (size_t)grow * 128 + kh * 64 + cg * 4);
            else          sts_zero16(dst);
        }
        asm volatile("cp.async.commit_group;" ::: "memory");
    };

    prefetchA(0, bufA[0]);

    for (int s = 0; s < nstg; s++) {
        const int p = s & 1;
        __syncthreads();
        {
            int blk = s >> 1, kh = s & 1;
            const char* bsrc = (const char*)Bt + ((size_t)(tile0 + blk) * 2 + kh) * 32768;
            #pragma unroll
            for (int i = 0; i < 8; i++) {
                uint32_t t = (uint32_t)(tid + i * 256) * 16u;
                cp_async16(sb + OFF_B + t, bsrc + t);
            }
            asm volatile("cp.async.commit_group;" ::: "memory");
        }
        asm volatile("cp.async.wait_group 1;" ::: "memory");
        // in-place convert: raw fp32 -> [hi 128B | lo 128B] per 256B row slot
        {
            int blk = s >> 1;
            const float* dgp = Dp[blk];
            #pragma unroll
            for (int h = 0; h < 2; h++) {       // disjoint row halves: 0-63 / 64-127
                float4 raw[4]; float scs[4];
                #pragma unroll
                for (int i = 0; i < 4; i++) {
                    int g = h * 1024 + tid + i * 256;
                    raw[i] = lds_f4(bufA[p] + (uint32_t)g * 16u);
                    int grow = m0 + (g >> 4);
                    scs[i] = 1.f;
                    if (dgp != nullptr && grow < M) scs[i] = 1.f / fmaxf(__ldg(&dgp[grow]), 1.f);
                }
                __syncthreads();
                #pragma unroll
                for (int i = 0; i < 4; i++) {
                    int g = h * 1024 + tid + i * 256;
                    int r = g >> 4, cg = g & 15;
                    float x0 = raw[i].x * scs[i], x1 = raw[i].y * scs[i];
                    float x2 = raw[i].z * scs[i], x3 = raw[i].w * scs[i];
                    __nv_bfloat162 h01 = __floats2bfloat162_rn(x0, x1);
                    __nv_bfloat162 h23 = __floats2bfloat162_rn(x2, x3);
                    float2 f01 = __bfloat1622float2(h01), f23 = __bfloat1622float2(h23);
                    __nv_bfloat162 l01 = __floats2bfloat162_rn(x0 - f01.x, x1 - f01.y);
                    __nv_bfloat162 l23 = __floats2bfloat162_rn(x2 - f23.x, x3 - f23.y);
                    uint32_t base = bufA[p] + (uint32_t)r * 256u
                                  + (uint32_t)((((cg >> 1) ^ (r & 7)) << 4) + ((cg & 1) << 3));
                    sts_u2(base,        bf2u(h01), bf2u(h23));
                    sts_u2(base + 128u, bf2u(l01), bf2u(l23));
                }
            }
        }
        asm volatile("cp.async.wait_group 0;" ::: "memory");
        __syncthreads();
        if (s + 1 < nstg) prefetchA(s + 1, bufA[1 - p]);

        #pragma unroll
        for (int ks = 0; ks < 4; ks++) {
            uint32_t ah[2][4], al[2][4];
            #pragma unroll
            for (int mt = 0; mt < 2; mt++) {
                int r = mw * 32 + mt * 16 + a_rowl;
                uint32_t base = bufA[p] + (uint32_t)r * 256u
                              + (uint32_t)(((2 * ks + a_half) ^ (r & 7)) << 4);
                ldsm_x4(ah[mt], base);
                ldsm_x4(al[mt], base + 128u);
            }
            #pragma unroll
            for (int nb = 0; nb < 4; nb++) {
                int r = nw * 64 + nb * 16 + b_rowl;
                uint32_t base = sb + OFF_B + (uint32_t)r * 256u
                              + (uint32_t)(((2 * ks + b_half) ^ (r & 7)) << 4);
                uint32_t bh[4], bl[4];
                ldsm_x4(bh, base);
                ldsm_x4(bl, base + 128u);
                #pragma unroll
                for (int mt = 0; mt < 2; mt++) {
                    mma_bf16(acc[mt][nb * 2 + 0], ah[mt], bh[0], bh[1]);
                    mma_bf16(acc[mt][nb * 2 + 1], ah[mt], bh[2], bh[3]);
                    mma_bf16(acc[mt][nb * 2 + 0], ah[mt], bl[0], bl[1]);
                    mma_bf16(acc[mt][nb * 2 + 1], ah[mt], bl[2], bl[3]);
                    mma_bf16(acc[mt][nb * 2 + 0], al[mt], bh[0], bh[1]);
                    mma_bf16(acc[mt][nb * 2 + 1], al[mt], bh[2], bh[3]);
                }
            }
        }
    }

    // ---- epilogue: relu(acc+bias) @ Wproj, shfl-reduce, red.add to pattr/papp ----
    const float* bias_s = (const float*)(smem + OFF_BIAS);
    const float* pw = (const float*)(smem + OFF_PW);
    #pragma unroll
    for (int mt = 0; mt < 2; mt++) {
        float p0[4] = {0.f, 0.f, 0.f, 0.f};
        float p1[4] = {0.f, 0.f, 0.f, 0.f};
        #pragma unroll
        for (int nt = 0; nt < 8; nt++) {
            int col = nw * 64 + nt * 8 + (lane & 3) * 2;
            float b0 = bias_s[col], b1v = bias_s[col + 1];
            float vx = fmaxf(acc[mt][nt][0] + b0, 0.f);
            float vy = fmaxf(acc[mt][nt][1] + b1v, 0.f);
            float vz = fmaxf(acc[mt][nt][2] + b0, 0.f);
            float vw = fmaxf(acc[mt][nt][3] + b1v, 0.f);
            #pragma unroll
            for (int c = 0; c < 4; c++) {
                p0[c] += vx * pw[col * 4 + c] + vy * pw[(col + 1) * 4 + c];
                p1[c] += vz * pw[col * 4 + c] + vw * pw[(col + 1) * 4 + c];
            }
        }
        #pragma unroll
        for (int c = 0; c < 4; c++) {
            p0[c] += __shfl_xor_sync(0xffffffffu, p0[c], 1);
            p0[c] += __shfl_xor_sync(0xffffffffu, p0[c], 2);
            p1[c] += __shfl_xor_sync(0xffffffffu, p1[c], 1);
            p1[c] += __shfl_xor_sync(0xffffffffu, p1[c], 2);
        }
        if ((lane & 3) == 0) {
            int r0 = m0 + mw * 32 + mt * 16 + (lane >> 2);
            if (is_app) {
                if (r0 < M)     red_add_v4(papp + (size_t)r0 * 4, make_float4(p0[0], p0[1], p0[2], p0[3]));
                if (r0 + 8 < M) red_add_v4(papp + (size_t)(r0 + 8) * 4, make_float4(p1[0], p1[1], p1[2], p1[3]));
            } else {
                if (r0 < M)     red_add_v2(pattr + (size_t)r0 * 2, p0[0], p0[1]);
                if (r0 + 8 < M) red_add_v2(pattr + (size_t)(r0 + 8) * 2, p1[0], p1[1]);
            }
        }
    }
}

// ---------------- fused layer-2 aggregation + finalize (CSR, no atomics) ----------------
__global__ void __launch_bounds__(256) final_kernel(
    const int* __restrict__ src1, const int* __restrict__ src2,
    const float* __restrict__ ew1, const float* __restrict__ ew2,
    float* __restrict__ out)
{
    int v = blockIdx.x * 256 + threadIdx.x;
    if (v >= N_APP) return;
    int g1 = BASE1 + v, g2 = BASE2 + v;
    float a0 = 0.f, a1 = 0.f;
    int s1 = g_row[g1], n1 = g_cnt[g1];
    #pragma unroll 4
    for (int i = 0; i < n1; i++) {
        int e = g_eid[s1 + i];
        int sp = src1[e];
        float w = ew1[e];
        a0 += w * g_pattr[sp * 2 + 0];
        a1 += w * g_pattr[sp * 2 + 1];
    }
    float b0 = 0.f, b1v = 0.f;
    int s2 = g_row[g2], n2 = g_cnt[g2];
    #pragma unroll 4
    for (int i = 0; i < n2; i++) {
        int e = g_eid[s2 + i];
        int sp = src2[e];
        float w = ew2[e];
        b0  += w * g_papp[sp * 4 + 2];
        b1v += w * g_papp[sp * 4 + 3];
    }
    float i1 = 1.f / fmaxf((float)n1, 1.f);
    float i2 = 1.f / fmaxf((float)n2, 1.f);
    out[v * 2 + 0] = g_papp[v * 4 + 0] + a0 * i1 + b0 * i2 + g_bce[0];
    out[v * 2 + 1] = g_papp[v * 4 + 1] + a1 * i1 + b1v * i2 + g_bce[1];
}

// ---------------- launch ----------------
extern "C" void kernel_launch(void* const* d_in, const int* in_sizes, int n_in,
                              void* d_out, int out_size)
{
    const float* x_app   = (const float*)d_in[0];
    const float* x_attr  = (const float*)d_in[1];
    const float* ew0     = (const float*)d_in[2];
    const float* ew1     = (const float*)d_in[3];
    const float* ew2     = (const float*)d_in[4];
    const float* Wself1  = (const float*)d_in[5];
    const float* Wneigh1 = (const float*)d_in[6];
    const float* b1      = (const float*)d_in[7];
    const float* Wself2  = (const float*)d_in[8];
    const float* Wneigh2 = (const float*)d_in[9];
    const float* b2      = (const float*)d_in[10];
    const float* Wc      = (const float*)d_in[11];
    const float* bc      = (const float*)d_in[12];
    const int* src0 = (const int*)d_in[13];
    const int* dst0 = (const int*)d_in[14];
    const int* src1 = (const int*)d_in[15];
    const int* dst1 = (const int*)d_in[16];
    const int* src2 = (const int*)d_in[17];
    const int* dst2 = (const int*)d_in[18];
    float* out = (float*)d_out;
    const int E = in_sizes[2];

    float *n0, *n1, *n2, *pattr, *papp, *degF, *bsum1, *Wn1c, *Wapp4;
    int *cnt;
    uint2 *Bt;
    cudaGetSymbolAddress((void**)&n0, g_n0);
    cudaGetSymbolAddress((void**)&n1, g_n1);
    cudaGetSymbolAddress((void**)&n2, g_n2);
    cudaGetSymbolAddress((void**)&pattr, g_pattr);
    cudaGetSymbolAddress((void**)&papp, g_papp);
    cudaGetSymbolAddress((void**)&degF, g_degF);
    cudaGetSymbolAddress((void**)&cnt, g_cnt);
    cudaGetSymbolAddress((void**)&bsum1, g_bsum1);
    cudaGetSymbolAddress((void**)&Wn1c, g_Wn1c);
    cudaGetSymbolAddress((void**)&Wapp4, g_Wapp4);
    cudaGetSymbolAddress((void**)&Bt, g_Bt);

    cudaFuncSetAttribute(gemm_fused_all, cudaFuncAttributeMaxDynamicSharedMemorySize, GEMM_SMEM);

    cudaMemsetAsync(cnt, 0, sizeof(g_cnt), 0);
    cudaMemsetAsync(pattr, 0, sizeof(g_pattr), 0);
    cudaMemsetAsync(papp, 0, sizeof(g_papp), 0);

    prep_kernel<<<1, 256>>>(b1, Wself2, Wneigh2, b2, Wc, bc);
    prep_weights<<<5, 256>>>(Wself1, Wneigh1);

    // CSR build
    int eb3 = (3 * E + 255) / 256;
    count_kernel<<<eb3, 256>>>(dst0, dst1, dst2, E);
    scan1_kernel<<<NBLK_SCAN, 256>>>();
    scan2_kernel<<<1, 256>>>();
    scan3_kernel<<<(N_TOT + 255) / 256, 256>>>();
    fill_kernel<<<eb3, 256>>>(dst0, dst1, dst2, E);

    // layer-1 aggregation (warp per node, single write, no feature atomics)
    agg_kernel<<<(N_TOT * 32 + 255) / 256, 256>>>(
        (const float4*)x_app, (const float4*)x_attr,
        src0, src1, src2, ew0, ew1, ew2);

    // merged layer-1 GEMMs + fused layer-2 projection
    gemm_fused_all<<<NB_ATTR + NB_APP, 256, GEMM_SMEM>>>(
        x_attr, x_app, n0, degF, n1, degF + BASE1, n2, degF + BASE2,
        b1, bsum1, Wn1c, Wapp4, Bt, pattr, papp);

    // fused layer-2 aggregation + classify
    final_kernel<<<(N_APP + 255) / 256, 256>>>(src1, src2, ew1, ew2, out);
}

// round 9
// speedup vs baseline: 2.1017x; 1.2349x over previous
#include <cuda_runtime.h>
#include <cuda_bf16.h>
#include <cstdint>

// Problem constants
#define N_APP  100000
#define N_ATTR 50000
#define D      128
#define NB_ATTR 391   // ceil(50000/128)
#define NB_APP  782   // ceil(100000/128)
#define N_TOT  250000 // concatenated node space: [attr(rel0) | app(rel1) | app(rel2)]
#define BASE1  50000
#define BASE2  150000
#define EMAX   500000
#define NBLK_SCAN 245 // ceil(250000/1024)

// ---------------- device scratch (no allocation allowed) ----------------
// pre-split aggregated neighbor features: per node 512B = [kh0: hi128|lo128][kh1: hi128|lo128],
// bf16, pre-scaled by 1/max(deg,1), chunk-XOR swizzled by (node&7) — the GEMM's smem layout.
__device__ uint2 g_s0[(size_t)N_ATTR * 64];
__device__ uint2 g_s1[(size_t)N_APP * 64];
__device__ uint2 g_s2[(size_t)N_APP * 64];
__device__ float g_pattr[(size_t)N_ATTR * 2];
__device__ float g_papp[(size_t)N_APP * 4];
__device__ int   g_cnt[N_TOT];
__device__ int   g_row[N_TOT];
__device__ int   g_cur[N_TOT];
__device__ int   g_bsum[256];
__device__ uint2 g_pack[3 * EMAX];   // CSR-ordered (src, ew-bits) records
__device__ float g_bsum1[D];       // b1[1]+b1[2]
__device__ float g_Wn1c[D * 2];    // Wneigh2[1] @ Wc
__device__ float g_Wapp4[D * 4];   // cols 0..1: (Wself2[1]+Wself2[2])@Wc ; cols 2..3: Wneigh2[2]@Wc
__device__ float g_bce[2];         // (b2[1]+b2[2])@Wc + bc
// bf16 weight tiles, merged hi/lo row-local layout (see prep_weights)
__device__ uint2 g_Bt[5 * 2 * 4096];

// ---------------- PTX helpers ----------------
__device__ __forceinline__ uint32_t smem_u32(const void* p) {
    uint32_t a;
    asm("{ .reg .u64 t; cvta.to.shared.u64 t, %1; cvt.u32.u64 %0, t; }" : "=r"(a) : "l"(p));
    return a;
}
__device__ __forceinline__ void ldsm_x4(uint32_t* r, uint32_t addr) {
    asm volatile("ldmatrix.sync.aligned.m8n8.x4.shared.b16 {%0,%1,%2,%3}, [%4];"
                 : "=r"(r[0]), "=r"(r[1]), "=r"(r[2]), "=r"(r[3]) : "r"(addr));
}
__device__ __forceinline__ void mma_bf16(float* c, const uint32_t* a, uint32_t b0, uint32_t b1) {
    asm volatile("mma.sync.aligned.m16n8k16.row.col.f32.bf16.bf16.f32 "
                 "{%0,%1,%2,%3}, {%4,%5,%6,%7}, {%8,%9}, {%0,%1,%2,%3};"
                 : "+f"(c[0]), "+f"(c[1]), "+f"(c[2]), "+f"(c[3])
                 : "r"(a[0]), "r"(a[1]), "r"(a[2]), "r"(a[3]), "r"(b0), "r"(b1));
}
__device__ __forceinline__ void cp_async16(uint32_t dst, const void* src) {
    asm volatile("cp.async.cg.shared.global [%0], [%1], 16;" :: "r"(dst), "l"(src) : "memory");
}
__device__ __forceinline__ void sts_u2(uint32_t addr, uint32_t a, uint32_t b) {
    asm volatile("st.shared.v2.b32 [%0], {%1,%2};" :: "r"(addr), "r"(a), "r"(b));
}
__device__ __forceinline__ void sts_zero16(uint32_t addr) {
    asm volatile("st.shared.v4.b32 [%0], {%1,%1,%1,%1};" :: "r"(addr), "r"(0u));
}
__device__ __forceinline__ float4 lds_f4(uint32_t addr) {
    float4 v;
    asm volatile("ld.shared.v4.f32 {%0,%1,%2,%3}, [%4];"
                 : "=f"(v.x), "=f"(v.y), "=f"(v.z), "=f"(v.w) : "r"(addr));
    return v;
}
__device__ __forceinline__ uint32_t bf2u(__nv_bfloat162 v) {
    return *reinterpret_cast<uint32_t*>(&v);
}
__device__ __forceinline__ void red_add_v4(float* addr, float4 v) {
    asm volatile("red.global.add.v4.f32 [%0], {%1,%2,%3,%4};"
                 :: "l"(addr), "f"(v.x), "f"(v.y), "f"(v.z), "f"(v.w) : "memory");
}
__device__ __forceinline__ void red_add_v2(float* addr, float a, float b) {
    asm volatile("red.global.add.v2.f32 [%0], {%1,%2};"
                 :: "l"(addr), "f"(a), "f"(b) : "memory");
}

// ---------------- small-weight prep ----------------
__global__ void prep_kernel(const float* __restrict__ b1,
                            const float* __restrict__ Wself2, const float* __restrict__ Wneigh2,
                            const float* __restrict__ b2,
                            const float* __restrict__ Wc, const float* __restrict__ bc)
{
    int tid = threadIdx.x;
    if (tid < D) g_bsum1[tid] = b1[128 + tid] + b1[256 + tid];
    {
        int i = tid >> 1, j = tid & 1;
        float s_sc = 0.f, s_n2 = 0.f, s_n1 = 0.f;
        #pragma unroll 4
        for (int l = 0; l < D; l++) {
            float wc = Wc[l * 2 + j];
            s_sc += (Wself2[16384 + i * D + l] + Wself2[32768 + i * D + l]) * wc;
            s_n2 += Wneigh2[32768 + i * D + l] * wc;
            s_n1 += Wneigh2[16384 + i * D + l] * wc;
        }
        g_Wapp4[i * 4 + j]     = s_sc;
        g_Wapp4[i * 4 + 2 + j] = s_n2;
        g_Wn1c[i * 2 + j]      = s_n1;
    }
    if (tid < 2) {
        float s = bc[tid];
        for (int l = 0; l < D; l++) s += (b2[128 + l] + b2[256 + l]) * Wc[l * 2 + tid];
        g_bce[tid] = s;
    }
}

// ---------------- weight tiles: transpose + hi/lo bf16 split + merged row-local layout ----------------
__global__ void prep_weights(const float* __restrict__ Wself1, const float* __restrict__ Wneigh1)
{
    int m = blockIdx.x;
    int tid = threadIdx.x;
    for (int idx = tid; idx < 4096; idx += 256) {
        int n = idx >> 5;
        int cg = idx & 31;
        int k0 = cg * 4;
        float w[4];
        #pragma unroll
        for (int i = 0; i < 4; i++) {
            int k = k0 + i;
            float v;
            if      (m == 0) v = Wself1[k * D + n];
            else if (m == 1) v = Wneigh1[k * D + n];
            else if (m == 2) v = Wself1[16384 + k * D + n] + Wself1[32768 + k * D + n];
            else if (m == 3) v = Wneigh1[16384 + k * D + n];
            else             v = Wneigh1[32768 + k * D + n];
            w[i] = v;
        }
        __nv_bfloat162 h01 = __floats2bfloat162_rn(w[0], w[1]);
        __nv_bfloat162 h23 = __floats2bfloat162_rn(w[2], w[3]);
        float2 f01 = __bfloat1622float2(h01), f23 = __bfloat1622float2(h23);
        __nv_bfloat162 l01 = __floats2bfloat162_rn(w[0] - f01.x, w[1] - f01.y);
        __nv_bfloat162 l23 = __floats2bfloat162_rn(w[2] - f23.x, w[3] - f23.y);
        int half = cg >> 4;
        int cgi  = cg & 15;
        char* base = (char*)g_Bt + ((size_t)(m * 2 + half)) * 32768 + (size_t)n * 256;
        uint32_t sw = (uint32_t)((((cgi >> 1) ^ (n & 7)) << 4) + ((cgi & 1) << 3));
        *(uint2*)(base + sw)       = make_uint2(bf2u(h01), bf2u(h23));
        *(uint2*)(base + 128 + sw) = make_uint2(bf2u(l01), bf2u(l23));
    }
}

// ---------------- CSR build: count -> scan -> fill (packed records) ----------------
__global__ void count_kernel(const int* __restrict__ d0, const int* __restrict__ d1,
                             const int* __restrict__ d2, int E)
{
    int i = blockIdx.x * 256 + threadIdx.x;
    if (i < E)           atomicAdd(&g_cnt[d0[i]], 1);
    else if (i < 2 * E)  atomicAdd(&g_cnt[BASE1 + d1[i - E]], 1);
    else if (i < 3 * E)  atomicAdd(&g_cnt[BASE2 + d2[i - 2 * E]], 1);
}

__global__ void scan1_kernel()
{
    __shared__ int sh[8];
    int b = blockIdx.x, t = threadIdx.x;
    int base = b * 1024 + t * 4;
    int v[4];
    #pragma unroll
    for (int i = 0; i < 4; i++) v[i] = (base + i < N_TOT) ? g_cnt[base + i] : 0;
    int local = v[0] + v[1] + v[2] + v[3];
    int lane = t & 31, w = t >> 5;
    int inc = local;
    #pragma unroll
    for (int o = 1; o < 32; o <<= 1) {
        int x = __shfl_up_sync(0xffffffffu, inc, o);
        if (lane >= o) inc += x;
    }
    if (lane == 31) sh[w] = inc;
    __syncthreads();
    if (t == 0) {
        int run = 0;
        #pragma unroll
        for (int i = 0; i < 8; i++) { int x = sh[i]; sh[i] = run; run += x; }
        g_bsum[b] = run;
    }
    __syncthreads();
    int run = sh[w] + inc - local;
    #pragma unroll
    for (int i = 0; i < 4; i++) {
        if (base + i < N_TOT) g_row[base + i] = run;
        run += v[i];
    }
}

__global__ void scan2_kernel()
{
    __shared__ int sh[8];
    int t = threadIdx.x;
    int v = (t < NBLK_SCAN) ? g_bsum[t] : 0;
    int lane = t & 31, w = t >> 5;
    int inc = v;
    #pragma unroll
    for (int o = 1; o < 32; o <<= 1) {
        int x = __shfl_up_sync(0xffffffffu, inc, o);
        if (lane >= o) inc += x;
    }
    if (lane == 31) sh[w] = inc;
    __syncthreads();
    if (t == 0) {
        int run = 0;
        #pragma unroll
        for (int i = 0; i < 8; i++) { int x = sh[i]; sh[i] = run; run += x; }
    }
    __syncthreads();
    int excl = sh[w] + inc - v;
    if (t < NBLK_SCAN) g_bsum[t] = excl;
}

__global__ void scan3_kernel()
{
    int i = blockIdx.x * 256 + threadIdx.x;
    if (i >= N_TOT) return;
    int r = g_row[i] + g_bsum[i >> 10];
    g_row[i] = r;
    g_cur[i] = r;
}

__global__ void fill_kernel(const int* __restrict__ d0, const int* __restrict__ d1,
                            const int* __restrict__ d2,
                            const int* __restrict__ s0, const int* __restrict__ s1,
                            const int* __restrict__ s2,
                            const float* __restrict__ w0, const float* __restrict__ w1,
                            const float* __restrict__ w2, int E)
{
    int i = blockIdx.x * 256 + threadIdx.x;
    int gidx; uint2 rec;
    if (i < E)          { gidx = d0[i];                rec = make_uint2((uint32_t)s0[i], __float_as_uint(w0[i])); }
    else if (i < 2 * E) { int e = i - E;     gidx = BASE1 + d1[e]; rec = make_uint2((uint32_t)s1[e], __float_as_uint(w1[e])); }
    else if (i < 3 * E) { int e = i - 2 * E; gidx = BASE2 + d2[e]; rec = make_uint2((uint32_t)s2[e], __float_as_uint(w2[e])); }
    else return;
    int pos = atomicAdd(&g_cur[gidx], 1);
    g_pack[pos] = rec;
}

// ---------------- CSR aggregation: warp per node, emits pre-scaled hi/lo bf16 split ----------------
__global__ void __launch_bounds__(256) agg_kernel(
    const float4* __restrict__ x_app, const float4* __restrict__ x_attr)
{
    int gw = (blockIdx.x * 256 + threadIdx.x) >> 5;
    int lane = threadIdx.x & 31;
    if (gw >= N_TOT) return;
    const float4* feat; char* out; int v;
    if (gw < BASE1)      { feat = x_app;  out = (char*)g_s0; v = gw; }
    else if (gw < BASE2) { feat = x_attr; out = (char*)g_s1; v = gw - BASE1; }
    else                 { feat = x_app;  out = (char*)g_s2; v = gw - BASE2; }
    int start = g_row[gw], n = g_cnt[gw];
    float4 acc = make_float4(0.f, 0.f, 0.f, 0.f);
    for (int c = 0; c < n; c += 32) {
        int m = n - c; if (m > 32) m = 32;
        int s = 0; float w = 0.f;
        if (lane < m) {
            uint2 rec = __ldg(&g_pack[start + c + lane]);
            s = (int)rec.x;
            w = __uint_as_float(rec.y);
        }
        #pragma unroll 4
        for (int j = 0; j < m; j++) {
            int sj   = __shfl_sync(0xffffffffu, s, j);
            float wj = __shfl_sync(0xffffffffu, w, j);
            float4 t = feat[(size_t)sj * 32 + lane];
            acc.x += wj * t.x; acc.y += wj * t.y; acc.z += wj * t.z; acc.w += wj * t.w;
        }
    }
    // pre-scale by 1/max(deg,1), split hi/lo, write in GEMM smem layout
    float sc = 1.f / fmaxf((float)n, 1.f);
    float x0 = acc.x * sc, x1 = acc.y * sc, x2 = acc.z * sc, x3 = acc.w * sc;
    __nv_bfloat162 h01 = __floats2bfloat162_rn(x0, x1);
    __nv_bfloat162 h23 = __floats2bfloat162_rn(x2, x3);
    float2 f01 = __bfloat1622float2(h01), f23 = __bfloat1622float2(h23);
    __nv_bfloat162 l01 = __floats2bfloat162_rn(x0 - f01.x, x1 - f01.y);
    __nv_bfloat162 l23 = __floats2bfloat162_rn(x2 - f23.x, x3 - f23.y);
    int kh = lane >> 4;               // k = lane*4 .. lane*4+3
    int cg = lane & 15;
    uint32_t sw = (uint32_t)((((cg >> 1) ^ (v & 7)) << 4) + ((cg & 1) << 3));
    char* base = out + (size_t)v * 512 + kh * 256 + sw;
    *(uint2*)base         = make_uint2(bf2u(h01), bf2u(h23));
    *(uint2*)(base + 128) = make_uint2(bf2u(l01), bf2u(l23));
}

// ---------------- merged tensor-core GEMM + fused layer-2 projection ----------------
// Neighbor stages consume pre-split agg output (pure cp.async); only self stages convert.
#define OFF_A0    0
#define OFF_A1    32768
#define OFF_B     65536
#define OFF_BIAS  98304
#define OFF_PW    98816
#define GEMM_SMEM 100864

__global__ void __launch_bounds__(256, 2) gemm_fused_all(
    const float* __restrict__ x_attr, const float* __restrict__ x_app,
    const char* __restrict__ s0, const char* __restrict__ s1, const char* __restrict__ s2,
    const float* __restrict__ b1, const float* __restrict__ bsum1,
    const float* __restrict__ Wn1c, const float* __restrict__ Wapp4,
    const uint2* __restrict__ Bt,
    float* __restrict__ pattr, float* __restrict__ papp)
{
    extern __shared__ __align__(1024) char smem[];
    const uint32_t sb = smem_u32(smem);
    const int tid = threadIdx.x;
    const int wid = tid >> 5, lane = tid & 31;
    const int mw = wid >> 1;
    const int nw = wid & 1;

    const bool is_app = (int)blockIdx.x >= NB_ATTR;
    const int bid = is_app ? (int)blockIdx.x - NB_ATTR : (int)blockIdx.x;
    const int m0 = bid * 128;
    const int M = is_app ? N_APP : N_ATTR;
    const int nstg = is_app ? 6 : 4;

    const float* Aself = is_app ? x_app : x_attr;
    const char* Asplit[3];
    int tile0;
    if (is_app) { Asplit[0] = nullptr; Asplit[1] = s1; Asplit[2] = s2; tile0 = 2; }
    else        { Asplit[0] = nullptr; Asplit[1] = s0; Asplit[2] = nullptr; tile0 = 0; }
    const float* bias = is_app ? bsum1 : b1;

    if (tid < 128) ((float*)(smem + OFF_BIAS))[tid] = bias[tid];
    for (int idx = tid; idx < 512; idx += 256) {
        int r = idx >> 2, c = idx & 3;
        ((float*)(smem + OFF_PW))[idx] = is_app ? Wapp4[idx] : (c < 2 ? Wn1c[r * 2 + c] : 0.f);
    }

    float acc[2][8][4];
    #pragma unroll
    for (int i = 0; i < 2; i++)
        #pragma unroll
        for (int j = 0; j < 8; j++)
            #pragma unroll
            for (int q = 0; q < 4; q++) acc[i][j][q] = 0.f;

    const int a_rowl = lane & 15;
    const int a_half = lane >> 4;
    const int b_rowl = (lane & 7) + ((lane >> 4) << 3);
    const int b_half = (lane >> 3) & 1;

    const uint32_t bufA[2] = { sb + OFF_A0, sb + OFF_A1 };

    auto prefetchA = [&](int s, uint32_t buf) {
        int blk = s >> 1, kh = s & 1;
        if (blk == 0) {
            #pragma unroll
            for (int i = 0; i < 8; i++) {
                int g = tid + i * 256;
                int r = g >> 4, cg = g & 15;
                int grow = m0 + r;
                uint32_t dst = buf + (uint32_t)g * 16u;
                if (grow < M) cp_async16(dst, Aself + (size_t)grow * 128 + kh * 64 + cg * 4);
                else          sts_zero16(dst);
            }
        } else {
            const char* S = Asplit[blk];
            #pragma unroll
            for (int i = 0; i < 8; i++) {
                int g = tid + i * 256;
                int r = g >> 4, cg = g & 15;
                int grow = m0 + r;
                uint32_t dst = buf + (uint32_t)g * 16u;
                if (grow < M) cp_async16(dst, S + (size_t)grow * 512 + kh * 256 + cg * 16);
                else          sts_zero16(dst);
            }
        }
        asm volatile("cp.async.commit_group;" ::: "memory");
    };

    prefetchA(0, bufA[0]);

    for (int s = 0; s < nstg; s++) {
        const int p = s & 1;
        __syncthreads();
        {
            int kh = s & 1;
            const char* bsrc = (const char*)Bt + ((size_t)(tile0 + (s >> 1)) * 2 + kh) * 32768;
            #pragma unroll
            for (int i = 0; i < 8; i++) {
                uint32_t t = (uint32_t)(tid + i * 256) * 16u;
                cp_async16(sb + OFF_B + t, bsrc + t);
            }
            asm volatile("cp.async.commit_group;" ::: "memory");
        }
        if (s < 2) {
            // self stage: raw fp32 -> in-place hi/lo bf16 convert
            asm volatile("cp.async.wait_group 1;" ::: "memory");
            #pragma unroll
            for (int h = 0; h < 2; h++) {       // disjoint row halves: 0-63 / 64-127
                float4 raw[4];
                #pragma unroll
                for (int i = 0; i < 4; i++) {
                    int g = h * 1024 + tid + i * 256;
                    raw[i] = lds_f4(bufA[p] + (uint32_t)g * 16u);
                }
                __syncthreads();
                #pragma unroll
                for (int i = 0; i < 4; i++) {
                    int g = h * 1024 + tid + i * 256;
                    int r = g >> 4, cg = g & 15;
                    __nv_bfloat162 h01 = __floats2bfloat162_rn(raw[i].x, raw[i].y);
                    __nv_bfloat162 h23 = __floats2bfloat162_rn(raw[i].z, raw[i].w);
                    float2 f01 = __bfloat1622float2(h01), f23 = __bfloat1622float2(h23);
                    __nv_bfloat162 l01 = __floats2bfloat162_rn(raw[i].x - f01.x, raw[i].y - f01.y);
                    __nv_bfloat162 l23 = __floats2bfloat162_rn(raw[i].z - f23.x, raw[i].w - f23.y);
                    uint32_t base = bufA[p] + (uint32_t)r * 256u
                                  + (uint32_t)((((cg >> 1) ^ (r & 7)) << 4) + ((cg & 1) << 3));
                    sts_u2(base,        bf2u(h01), bf2u(h23));
                    sts_u2(base + 128u, bf2u(l01), bf2u(l23));
                }
            }
        }
        asm volatile("cp.async.wait_group 0;" ::: "memory");
        __syncthreads();
        if (s + 1 < nstg) prefetchA(s + 1, bufA[1 - p]);

        #pragma unroll
        for (int ks = 0; ks < 4; ks++) {
            uint32_t ah[2][4], al[2][4];
            #pragma unroll
            for (int mt = 0; mt < 2; mt++) {
                int r = mw * 32 + mt * 16 + a_rowl;
                uint32_t base = bufA[p] + (uint32_t)r * 256u
                              + (uint32_t)(((2 * ks + a_half) ^ (r & 7)) << 4);
                ldsm_x4(ah[mt], base);
                ldsm_x4(al[mt], base + 128u);
            }
            #pragma unroll
            for (int nb = 0; nb < 4; nb++) {
                int r = nw * 64 + nb * 16 + b_rowl;
                uint32_t base = sb + OFF_B + (uint32_t)r * 256u
                              + (uint32_t)(((2 * ks + b_half) ^ (r & 7)) << 4);
                uint32_t bh[4], bl[4];
                ldsm_x4(bh, base);
                ldsm_x4(bl, base + 128u);
                #pragma unroll
                for (int mt = 0; mt < 2; mt++) {
                    mma_bf16(acc[mt][nb * 2 + 0], ah[mt], bh[0], bh[1]);
                    mma_bf16(acc[mt][nb * 2 + 1], ah[mt], bh[2], bh[3]);
                    mma_bf16(acc[mt][nb * 2 + 0], ah[mt], bl[0], bl[1]);
                    mma_bf16(acc[mt][nb * 2 + 1], ah[mt], bl[2], bl[3]);
                    mma_bf16(acc[mt][nb * 2 + 0], al[mt], bh[0], bh[1]);
                    mma_bf16(acc[mt][nb * 2 + 1], al[mt], bh[2], bh[3]);
                }
            }
        }
    }

    // ---- epilogue: relu(acc+bias) @ Wproj, shfl-reduce, red.add to pattr/papp ----
    const float* bias_s = (const float*)(smem + OFF_BIAS);
    const float* pw = (const float*)(smem + OFF_PW);
    #pragma unroll
    for (int mt = 0; mt < 2; mt++) {
        float p0[4] = {0.f, 0.f, 0.f, 0.f};
        float p1[4] = {0.f, 0.f, 0.f, 0.f};
        #pragma unroll
        for (int nt = 0; nt < 8; nt++) {
            int col = nw * 64 + nt * 8 + (lane & 3) * 2;
            float b0 = bias_s[col], b1v = bias_s[col + 1];
            float vx = fmaxf(acc[mt][nt][0] + b0, 0.f);
            float vy = fmaxf(acc[mt][nt][1] + b1v, 0.f);
            float vz = fmaxf(acc[mt][nt][2] + b0, 0.f);
            float vw = fmaxf(acc[mt][nt][3] + b1v, 0.f);
            #pragma unroll
            for (int c = 0; c < 4; c++) {
                p0[c] += vx * pw[col * 4 + c] + vy * pw[(col + 1) * 4 + c];
                p1[c] += vz * pw[col * 4 + c] + vw * pw[(col + 1) * 4 + c];
            }
        }
        #pragma unroll
        for (int c = 0; c < 4; c++) {
            p0[c] += __shfl_xor_sync(0xffffffffu, p0[c], 1);
            p0[c] += __shfl_xor_sync(0xffffffffu, p0[c], 2);
            p1[c] += __shfl_xor_sync(0xffffffffu, p1[c], 1);
            p1[c] += __shfl_xor_sync(0xffffffffu, p1[c], 2);
        }
        if ((lane & 3) == 0) {
            int r0 = m0 + mw * 32 + mt * 16 + (lane >> 2);
            if (is_app) {
                if (r0 < M)     red_add_v4(papp + (size_t)r0 * 4, make_float4(p0[0], p0[1], p0[2], p0[3]));
                if (r0 + 8 < M) red_add_v4(papp + (size_t)(r0 + 8) * 4, make_float4(p1[0], p1[1], p1[2], p1[3]));
            } else {
                if (r0 < M)     red_add_v2(pattr + (size_t)r0 * 2, p0[0], p0[1]);
                if (r0 + 8 < M) red_add_v2(pattr + (size_t)(r0 + 8) * 2, p1[0], p1[1]);
            }
        }
    }
}

// ---------------- fused layer-2 aggregation + finalize (packed CSR, no atomics) ----------------
__global__ void __launch_bounds__(256) final_kernel(float* __restrict__ out)
{
    int v = blockIdx.x * 256 + threadIdx.x;
    if (v >= N_APP) return;
    int g1 = BASE1 + v, g2 = BASE2 + v;
    float a0 = 0.f, a1 = 0.f;
    int s1 = g_row[g1], n1 = g_cnt[g1];
    #pragma unroll 4
    for (int i = 0; i < n1; i++) {
        uint2 rec = __ldg(&g_pack[s1 + i]);
        int sp = (int)rec.x;
        float w = __uint_as_float(rec.y);
        a0 += w * g_pattr[sp * 2 + 0];
        a1 += w * g_pattr[sp * 2 + 1];
    }
    float b0 = 0.f, b1v = 0.f;
    int s2 = g_row[g2], n2 = g_cnt[g2];
    #pragma unroll 4
    for (int i = 0; i < n2; i++) {
        uint2 rec = __ldg(&g_pack[s2 + i]);
        int sp = (int)rec.x;
        float w = __uint_as_float(rec.y);
        b0  += w * g_papp[sp * 4 + 2];
        b1v += w * g_papp[sp * 4 + 3];
    }
    float i1 = 1.f / fmaxf((float)n1, 1.f);
    float i2 = 1.f / fmaxf((float)n2, 1.f);
    out[v * 2 + 0] = g_papp[v * 4 + 0] + a0 * i1 + b0 * i2 + g_bce[0];
    out[v * 2 + 1] = g_papp[v * 4 + 1] + a1 * i1 + b1v * i2 + g_bce[1];
}

// ---------------- launch ----------------
extern "C" void kernel_launch(void* const* d_in, const int* in_sizes, int n_in,
                              void* d_out, int out_size)
{
    const float* x_app   = (const float*)d_in[0];
    const float* x_attr  = (const float*)d_in[1];
    const float* ew0     = (const float*)d_in[2];
    const float* ew1     = (const float*)d_in[3];
    const float* ew2     = (const float*)d_in[4];
    const float* Wself1  = (const float*)d_in[5];
    const float* Wneigh1 = (const float*)d_in[6];
    const float* b1      = (const float*)d_in[7];
    const float* Wself2  = (const float*)d_in[8];
    const float* Wneigh2 = (const float*)d_in[9];
    const float* b2      = (const float*)d_in[10];
    const float* Wc      = (const float*)d_in[11];
    const float* bc      = (const float*)d_in[12];
    const int* src0 = (const int*)d_in[13];
    const int* dst0 = (const int*)d_in[14];
    const int* src1 = (const int*)d_in[15];
    const int* dst1 = (const int*)d_in[16];
    const int* src2 = (const int*)d_in[17];
    const int* dst2 = (const int*)d_in[18];
    float* out = (float*)d_out;
    const int E = in_sizes[2];

    float *pattr, *papp, *bsum1, *Wn1c, *Wapp4;
    int *cnt;
    uint2 *Bt, *s0, *s1, *s2;
    cudaGetSymbolAddress((void**)&s0, g_s0);
    cudaGetSymbolAddress((void**)&s1, g_s1);
    cudaGetSymbolAddress((void**)&s2, g_s2);
    cudaGetSymbolAddress((void**)&pattr, g_pattr);
    cudaGetSymbolAddress((void**)&papp, g_papp);
    cudaGetSymbolAddress((void**)&cnt, g_cnt);
    cudaGetSymbolAddress((void**)&bsum1, g_bsum1);
    cudaGetSymbolAddress((void**)&Wn1c, g_Wn1c);
    cudaGetSymbolAddress((void**)&Wapp4, g_Wapp4);
    cudaGetSymbolAddress((void**)&Bt, g_Bt);

    cudaFuncSetAttribute(gemm_fused_all, cudaFuncAttributeMaxDynamicSharedMemorySize, GEMM_SMEM);

    cudaMemsetAsync(cnt, 0, sizeof(g_cnt), 0);
    cudaMemsetAsync(pattr, 0, sizeof(g_pattr), 0);
    cudaMemsetAsync(papp, 0, sizeof(g_papp), 0);

    prep_kernel<<<1, 256>>>(b1, Wself2, Wneigh2, b2, Wc, bc);
    prep_weights<<<5, 256>>>(Wself1, Wneigh1);

    // CSR build with packed (src, ew) records
    int eb3 = (3 * E + 255) / 256;
    count_kernel<<<eb3, 256>>>(dst0, dst1, dst2, E);
    scan1_kernel<<<NBLK_SCAN, 256>>>();
    scan2_kernel<<<1, 256>>>();
    scan3_kernel<<<(N_TOT + 255) / 256, 256>>>();
    fill_kernel<<<eb3, 256>>>(dst0, dst1, dst2, src0, src1, src2, ew0, ew1, ew2, E);

    // layer-1 aggregation: contiguous packed reads, pre-scaled pre-split bf16 output
    agg_kernel<<<(N_TOT * 32 + 255) / 256, 256>>>(
        (const float4*)x_app, (const float4*)x_attr);

    // merged layer-1 GEMMs + fused layer-2 projection
    gemm_fused_all<<<NB_ATTR + NB_APP, 256, GEMM_SMEM>>>(
        x_attr, x_app, (const char*)s0, (const char*)s1, (const char*)s2,
        b1, bsum1, Wn1c, Wapp4, Bt, pattr, papp);

    // fused layer-2 aggregation + classify
    final_kernel<<<(N_APP + 255) / 256, 256>>>(out);
}